// round 1
// baseline (speedup 1.0000x reference)
#include <cuda_runtime.h>
#include <cuda_bf16.h>

#define BATCH 8
#define CCH   512
#define LSEQ  1024
#define GRPS  32
#define CPG   16      // channels per group
#define HEADS 8
#define DH    64
#define INNER 512
#define KDIM  512     // GEMM K dim (channels)
#define QK_SCALE 0.125f  // dh^-0.5, applied to BOTH q and k

// ---------------- scratch (no allocs allowed) ----------------
__device__ float g_hn [BATCH * CCH   * LSEQ];   // group-normed x
__device__ float g_qkv[BATCH * 3*INNER * LSEQ]; // rows: [0,512)=q*s, [512,1024)=k*s, [1024,1536)=v
__device__ float g_att[BATCH * INNER * LSEQ];   // attention output

// ---------------- 1) GroupNorm ----------------
__global__ void gn_kernel(const float* __restrict__ x,
                          const float* __restrict__ gamma,
                          const float* __restrict__ beta,
                          float* __restrict__ hn)
{
    const int b = blockIdx.x / GRPS;
    const int g = blockIdx.x % GRPS;
    const float* xp = x  + ((size_t)b * CCH + g * CPG) * LSEQ;
    float*       hp = hn + ((size_t)b * CCH + g * CPG) * LSEQ;
    const int N = CPG * LSEQ; // 16384

    float s1 = 0.f, s2 = 0.f;
    for (int e = threadIdx.x; e < N; e += blockDim.x) {
        float v = xp[e];
        s1 += v; s2 += v * v;
    }
    __shared__ float r1[32], r2[32];
    #pragma unroll
    for (int o = 16; o > 0; o >>= 1) {
        s1 += __shfl_down_sync(0xffffffffu, s1, o);
        s2 += __shfl_down_sync(0xffffffffu, s2, o);
    }
    int wid = threadIdx.x >> 5, lid = threadIdx.x & 31;
    if (lid == 0) { r1[wid] = s1; r2[wid] = s2; }
    __syncthreads();
    if (wid == 0) {
        int nw = blockDim.x >> 5;
        s1 = (lid < nw) ? r1[lid] : 0.f;
        s2 = (lid < nw) ? r2[lid] : 0.f;
        #pragma unroll
        for (int o = 16; o > 0; o >>= 1) {
            s1 += __shfl_down_sync(0xffffffffu, s1, o);
            s2 += __shfl_down_sync(0xffffffffu, s2, o);
        }
        if (lid == 0) { r1[0] = s1; r2[0] = s2; }
    }
    __syncthreads();
    const float mean = r1[0] / (float)N;
    const float var  = r2[0] / (float)N - mean * mean;
    const float rstd = rsqrtf(var + 1e-5f);
    for (int e = threadIdx.x; e < N; e += blockDim.x) {
        int c = g * CPG + (e >> 10);  // e / LSEQ
        hp[e] = (xp[e] - mean) * rstd * gamma[c] + beta[c];
    }
}

// ---------------- 2/4) SGEMM: C[b][m][n] = sum_k A[m][k]*B[b][k][n] (+bias, scale, resid) ----------------
// A: M x 512 row-major (weights, shared across batch)
// B: per-batch 512 x 1024 row-major, batch stride 512*1024
// C: Cp + b*cBatchStride + m*1024 + n
// rows m < scaleRows get multiplied by QK_SCALE after bias
template<int M, bool HAS_RESID>
__global__ __launch_bounds__(256)
void gemm_kernel(const float* __restrict__ A,
                 const float* __restrict__ B,
                 const float* __restrict__ bias,
                 const float* __restrict__ resid,
                 float* __restrict__ Cp,
                 int cBatchStride, int scaleRows)
{
    __shared__ float As[8][128];
    __shared__ float Bs[8][128];

    const int tx = threadIdx.x & 15;      // 0..15 -> n
    const int ty = threadIdx.x >> 4;      // 0..15 -> m
    const int m0 = blockIdx.y * 128;
    const int n0 = blockIdx.x * 128;
    const int b  = blockIdx.z;

    const float* Ab = A + (size_t)m0 * KDIM;
    const float* Bb = B + (size_t)b * KDIM * LSEQ + n0;

    float acc[8][8];
    #pragma unroll
    for (int p = 0; p < 8; p++)
        #pragma unroll
        for (int q = 0; q < 8; q++) acc[p][q] = 0.f;

    for (int k0 = 0; k0 < KDIM; k0 += 8) {
        #pragma unroll
        for (int i = 0; i < 4; i++) {
            int e  = threadIdx.x + i * 256;
            int kk = e & 7, m = e >> 3;
            As[kk][m] = Ab[(size_t)m * KDIM + k0 + kk];
        }
        #pragma unroll
        for (int i = 0; i < 4; i++) {
            int e  = threadIdx.x + i * 256;
            int n  = e & 127, kk = e >> 7;
            Bs[kk][n] = Bb[(size_t)(k0 + kk) * LSEQ + n];
        }
        __syncthreads();
        #pragma unroll
        for (int kk = 0; kk < 8; kk++) {
            float a[8], bb[8];
            #pragma unroll
            for (int p = 0; p < 8; p++) a[p]  = As[kk][ty * 8 + p];
            #pragma unroll
            for (int q = 0; q < 8; q++) bb[q] = Bs[kk][tx * 8 + q];
            #pragma unroll
            for (int p = 0; p < 8; p++)
                #pragma unroll
                for (int q = 0; q < 8; q++)
                    acc[p][q] += a[p] * bb[q];
        }
        __syncthreads();
    }

    float* Cb = Cp + (size_t)b * cBatchStride;
    #pragma unroll
    for (int p = 0; p < 8; p++) {
        const int m = m0 + ty * 8 + p;
        const float bi = bias[m];
        const float sc = (m < scaleRows) ? QK_SCALE : 1.0f;
        #pragma unroll
        for (int q = 0; q < 8; q++) {
            const int n = n0 + tx * 8 + q;
            float v = (acc[p][q] + bi) * sc;
            if (HAS_RESID)
                v += resid[(size_t)b * cBatchStride + (size_t)m * LSEQ + n];
            Cb[(size_t)m * LSEQ + n] = v;
        }
    }
}

// ---------------- 3) Flash attention: 1 thread = 1 query ----------------
__global__ __launch_bounds__(128)
void attn_kernel(const float* __restrict__ qkv, float* __restrict__ out)
{
    const int b = blockIdx.z;
    const int h = blockIdx.y;
    const int t = blockIdx.x * 128 + threadIdx.x;

    const float* Q = qkv + ((size_t)b * (3 * INNER) + h * DH) * LSEQ;
    const float* K = Q + (size_t)INNER     * LSEQ;
    const float* V = Q + (size_t)(2*INNER) * LSEQ;

    float q[DH];
    #pragma unroll
    for (int d = 0; d < DH; d++) q[d] = Q[(size_t)d * LSEQ + t];

    float o[DH];
    #pragma unroll
    for (int d = 0; d < DH; d++) o[d] = 0.f;
    float m = -1e30f, l = 0.f;

    __shared__ float Ks[64][68];
    __shared__ float Vs[64][68];

    for (int s0 = 0; s0 < LSEQ; s0 += 64) {
        __syncthreads();
        #pragma unroll
        for (int i = 0; i < 32; i++) {
            int e  = threadIdx.x + i * 128;
            int d  = e >> 6, si = e & 63;
            Ks[si][d] = K[(size_t)d * LSEQ + s0 + si];
            Vs[si][d] = V[(size_t)d * LSEQ + s0 + si];
        }
        __syncthreads();

        for (int si = 0; si < 64; si++) {
            const float4* kr = (const float4*)(&Ks[si][0]);
            float dot = 0.f;
            #pragma unroll
            for (int d4 = 0; d4 < 16; d4++) {
                float4 kk = kr[d4];
                dot += q[d4*4+0]*kk.x + q[d4*4+1]*kk.y
                     + q[d4*4+2]*kk.z + q[d4*4+3]*kk.w;
            }
            if (dot > m) {
                float corr = __expf(m - dot);
                l *= corr;
                #pragma unroll
                for (int d = 0; d < DH; d++) o[d] *= corr;
                m = dot;
            }
            float p = __expf(dot - m);
            l += p;
            const float4* vr = (const float4*)(&Vs[si][0]);
            #pragma unroll
            for (int d4 = 0; d4 < 16; d4++) {
                float4 vv = vr[d4];
                o[d4*4+0] += p * vv.x; o[d4*4+1] += p * vv.y;
                o[d4*4+2] += p * vv.z; o[d4*4+3] += p * vv.w;
            }
        }
    }

    const float inv = 1.f / l;
    float* O = out + ((size_t)b * INNER + h * DH) * LSEQ;
    #pragma unroll
    for (int d = 0; d < DH; d++) O[(size_t)d * LSEQ + t] = o[d] * inv;
}

// ---------------- launch ----------------
extern "C" void kernel_launch(void* const* d_in, const int* in_sizes, int n_in,
                              void* d_out, int out_size)
{
    const float* x     = (const float*)d_in[0];
    const float* gamma = (const float*)d_in[1];
    const float* beta  = (const float*)d_in[2];
    const float* Wq    = (const float*)d_in[3];
    const float* bq    = (const float*)d_in[4];
    const float* Wkv   = (const float*)d_in[5];
    const float* bkv   = (const float*)d_in[6];
    const float* Wo    = (const float*)d_in[7];
    const float* bo    = (const float*)d_in[8];
    float* out = (float*)d_out;

    float* hn;  cudaGetSymbolAddress((void**)&hn,  g_hn);
    float* qkv; cudaGetSymbolAddress((void**)&qkv, g_qkv);
    float* att; cudaGetSymbolAddress((void**)&att, g_att);

    // 1) GroupNorm
    gn_kernel<<<BATCH * GRPS, 256>>>(x, gamma, beta, hn);

    // 2) Q projection (all 512 rows scaled) and KV projection (first 512 rows = k scaled)
    {
        dim3 grid(LSEQ / 128, INNER / 128, BATCH);
        gemm_kernel<INNER, false><<<grid, 256>>>(Wq, hn, bq, nullptr,
                                                 qkv, 3 * INNER * LSEQ, INNER);
    }
    {
        dim3 grid(LSEQ / 128, (2 * INNER) / 128, BATCH);
        gemm_kernel<2 * INNER, false><<<grid, 256>>>(Wkv, hn, bkv, nullptr,
                                                     qkv + (size_t)INNER * LSEQ,
                                                     3 * INNER * LSEQ, INNER);
    }

    // 3) Attention
    {
        dim3 grid(LSEQ / 128, HEADS, BATCH);
        attn_kernel<<<grid, 128>>>(qkv, att);
    }

    // 4) Output projection + residual
    {
        dim3 grid(LSEQ / 128, CCH / 128, BATCH);
        gemm_kernel<CCH, true><<<grid, 256>>>(Wo, att, bo, x,
                                              out, CCH * LSEQ, 0);
    }
}

// round 2
// speedup vs baseline: 1.0004x; 1.0004x over previous
#include <cuda_runtime.h>
#include <cuda_bf16.h>

#define BATCH 8
#define CCH   512
#define LSEQ  1024
#define GRPS  32
#define CPG   16      // channels per group
#define HEADS 8
#define DH    64
#define INNER 512
#define KDIM  512     // GEMM K dim (channels)
#define QK_SCALE 0.125f  // dh^-0.5, applied to BOTH q and k

// ---------------- scratch (no allocs allowed) ----------------
__device__ float g_hn [BATCH * CCH   * LSEQ];   // group-normed x
__device__ float g_qkv[BATCH * 3*INNER * LSEQ]; // rows: [0,512)=q*s, [512,1024)=k*s, [1024,1536)=v
__device__ float g_att[BATCH * INNER * LSEQ];   // attention output

// ---------------- 1) GroupNorm ----------------
__global__ void gn_kernel(const float* __restrict__ x,
                          const float* __restrict__ gamma,
                          const float* __restrict__ beta,
                          float* __restrict__ hn)
{
    const int b = blockIdx.x / GRPS;
    const int g = blockIdx.x % GRPS;
    const float* xp = x  + ((size_t)b * CCH + g * CPG) * LSEQ;
    float*       hp = hn + ((size_t)b * CCH + g * CPG) * LSEQ;
    const int N = CPG * LSEQ; // 16384

    float s1 = 0.f, s2 = 0.f;
    for (int e = threadIdx.x; e < N; e += blockDim.x) {
        float v = xp[e];
        s1 += v; s2 += v * v;
    }
    __shared__ float r1[32], r2[32];
    #pragma unroll
    for (int o = 16; o > 0; o >>= 1) {
        s1 += __shfl_down_sync(0xffffffffu, s1, o);
        s2 += __shfl_down_sync(0xffffffffu, s2, o);
    }
    int wid = threadIdx.x >> 5, lid = threadIdx.x & 31;
    if (lid == 0) { r1[wid] = s1; r2[wid] = s2; }
    __syncthreads();
    if (wid == 0) {
        int nw = blockDim.x >> 5;
        s1 = (lid < nw) ? r1[lid] : 0.f;
        s2 = (lid < nw) ? r2[lid] : 0.f;
        #pragma unroll
        for (int o = 16; o > 0; o >>= 1) {
            s1 += __shfl_down_sync(0xffffffffu, s1, o);
            s2 += __shfl_down_sync(0xffffffffu, s2, o);
        }
        if (lid == 0) { r1[0] = s1; r2[0] = s2; }
    }
    __syncthreads();
    const float mean = r1[0] / (float)N;
    const float var  = r2[0] / (float)N - mean * mean;
    const float rstd = rsqrtf(var + 1e-5f);
    for (int e = threadIdx.x; e < N; e += blockDim.x) {
        int c = g * CPG + (e >> 10);  // e / LSEQ
        hp[e] = (xp[e] - mean) * rstd * gamma[c] + beta[c];
    }
}

// ---------------- 2/4) SGEMM: C[b][m][n] = sum_k A[m][k]*B[b][k][n] (+bias, scale, resid) ----------------
// A: M x 512 row-major (weights, shared across batch)
// B: per-batch 512 x 1024 row-major, batch stride 512*1024
// C: Cp + b*cBatchStride + m*1024 + n
// rows m < scaleRows get multiplied by QK_SCALE after bias
template<int M, bool HAS_RESID>
__global__ __launch_bounds__(256)
void gemm_kernel(const float* __restrict__ A,
                 const float* __restrict__ B,
                 const float* __restrict__ bias,
                 const float* __restrict__ resid,
                 float* __restrict__ Cp,
                 int cBatchStride, int scaleRows)
{
    __shared__ float As[8][128];
    __shared__ float Bs[8][128];

    const int tx = threadIdx.x & 15;      // 0..15 -> n
    const int ty = threadIdx.x >> 4;      // 0..15 -> m
    const int m0 = blockIdx.y * 128;
    const int n0 = blockIdx.x * 128;
    const int b  = blockIdx.z;

    const float* Ab = A + (size_t)m0 * KDIM;
    const float* Bb = B + (size_t)b * KDIM * LSEQ + n0;

    float acc[8][8];
    #pragma unroll
    for (int p = 0; p < 8; p++)
        #pragma unroll
        for (int q = 0; q < 8; q++) acc[p][q] = 0.f;

    for (int k0 = 0; k0 < KDIM; k0 += 8) {
        #pragma unroll
        for (int i = 0; i < 4; i++) {
            int e  = threadIdx.x + i * 256;
            int kk = e & 7, m = e >> 3;
            As[kk][m] = Ab[(size_t)m * KDIM + k0 + kk];
        }
        #pragma unroll
        for (int i = 0; i < 4; i++) {
            int e  = threadIdx.x + i * 256;
            int n  = e & 127, kk = e >> 7;
            Bs[kk][n] = Bb[(size_t)(k0 + kk) * LSEQ + n];
        }
        __syncthreads();
        #pragma unroll
        for (int kk = 0; kk < 8; kk++) {
            float a[8], bb[8];
            #pragma unroll
            for (int p = 0; p < 8; p++) a[p]  = As[kk][ty * 8 + p];
            #pragma unroll
            for (int q = 0; q < 8; q++) bb[q] = Bs[kk][tx * 8 + q];
            #pragma unroll
            for (int p = 0; p < 8; p++)
                #pragma unroll
                for (int q = 0; q < 8; q++)
                    acc[p][q] += a[p] * bb[q];
        }
        __syncthreads();
    }

    float* Cb = Cp + (size_t)b * cBatchStride;
    #pragma unroll
    for (int p = 0; p < 8; p++) {
        const int m = m0 + ty * 8 + p;
        const float bi = bias[m];
        const float sc = (m < scaleRows) ? QK_SCALE : 1.0f;
        #pragma unroll
        for (int q = 0; q < 8; q++) {
            const int n = n0 + tx * 8 + q;
            float v = (acc[p][q] + bi) * sc;
            if (HAS_RESID)
                v += resid[(size_t)b * cBatchStride + (size_t)m * LSEQ + n];
            Cb[(size_t)m * LSEQ + n] = v;
        }
    }
}

// ---------------- 3) Flash attention: 1 thread = 1 query ----------------
__global__ __launch_bounds__(128)
void attn_kernel(const float* __restrict__ qkv, float* __restrict__ out)
{
    const int b = blockIdx.z;
    const int h = blockIdx.y;
    const int t = blockIdx.x * 128 + threadIdx.x;

    const float* Q = qkv + ((size_t)b * (3 * INNER) + h * DH) * LSEQ;
    const float* K = Q + (size_t)INNER     * LSEQ;
    const float* V = Q + (size_t)(2*INNER) * LSEQ;

    float q[DH];
    #pragma unroll
    for (int d = 0; d < DH; d++) q[d] = Q[(size_t)d * LSEQ + t];

    float o[DH];
    #pragma unroll
    for (int d = 0; d < DH; d++) o[d] = 0.f;
    float m = -1e30f, l = 0.f;

    __shared__ float Ks[64][68];
    __shared__ float Vs[64][68];

    for (int s0 = 0; s0 < LSEQ; s0 += 64) {
        __syncthreads();
        #pragma unroll
        for (int i = 0; i < 32; i++) {
            int e  = threadIdx.x + i * 128;
            int d  = e >> 6, si = e & 63;
            Ks[si][d] = K[(size_t)d * LSEQ + s0 + si];
            Vs[si][d] = V[(size_t)d * LSEQ + s0 + si];
        }
        __syncthreads();

        for (int si = 0; si < 64; si++) {
            const float4* kr = (const float4*)(&Ks[si][0]);
            float dot = 0.f;
            #pragma unroll
            for (int d4 = 0; d4 < 16; d4++) {
                float4 kk = kr[d4];
                dot += q[d4*4+0]*kk.x + q[d4*4+1]*kk.y
                     + q[d4*4+2]*kk.z + q[d4*4+3]*kk.w;
            }
            if (dot > m) {
                float corr = __expf(m - dot);
                l *= corr;
                #pragma unroll
                for (int d = 0; d < DH; d++) o[d] *= corr;
                m = dot;
            }
            float p = __expf(dot - m);
            l += p;
            const float4* vr = (const float4*)(&Vs[si][0]);
            #pragma unroll
            for (int d4 = 0; d4 < 16; d4++) {
                float4 vv = vr[d4];
                o[d4*4+0] += p * vv.x; o[d4*4+1] += p * vv.y;
                o[d4*4+2] += p * vv.z; o[d4*4+3] += p * vv.w;
            }
        }
    }

    const float inv = 1.f / l;
    float* O = out + ((size_t)b * INNER + h * DH) * LSEQ;
    #pragma unroll
    for (int d = 0; d < DH; d++) O[(size_t)d * LSEQ + t] = o[d] * inv;
}

// ---------------- launch ----------------
extern "C" void kernel_launch(void* const* d_in, const int* in_sizes, int n_in,
                              void* d_out, int out_size)
{
    const float* x     = (const float*)d_in[0];
    const float* gamma = (const float*)d_in[1];
    const float* beta  = (const float*)d_in[2];
    const float* Wq    = (const float*)d_in[3];
    const float* bq    = (const float*)d_in[4];
    const float* Wkv   = (const float*)d_in[5];
    const float* bkv   = (const float*)d_in[6];
    const float* Wo    = (const float*)d_in[7];
    const float* bo    = (const float*)d_in[8];
    float* out = (float*)d_out;

    float* hn;  cudaGetSymbolAddress((void**)&hn,  g_hn);
    float* qkv; cudaGetSymbolAddress((void**)&qkv, g_qkv);
    float* att; cudaGetSymbolAddress((void**)&att, g_att);

    // 1) GroupNorm
    gn_kernel<<<BATCH * GRPS, 256>>>(x, gamma, beta, hn);

    // 2) Q projection (all 512 rows scaled) and KV projection (first 512 rows = k scaled)
    {
        dim3 grid(LSEQ / 128, INNER / 128, BATCH);
        gemm_kernel<INNER, false><<<grid, 256>>>(Wq, hn, bq, nullptr,
                                                 qkv, 3 * INNER * LSEQ, INNER);
    }
    {
        dim3 grid(LSEQ / 128, (2 * INNER) / 128, BATCH);
        gemm_kernel<2 * INNER, false><<<grid, 256>>>(Wkv, hn, bkv, nullptr,
                                                     qkv + (size_t)INNER * LSEQ,
                                                     3 * INNER * LSEQ, INNER);
    }

    // 3) Attention
    {
        dim3 grid(LSEQ / 128, HEADS, BATCH);
        attn_kernel<<<grid, 128>>>(qkv, att);
    }

    // 4) Output projection + residual
    {
        dim3 grid(LSEQ / 128, CCH / 128, BATCH);
        gemm_kernel<CCH, true><<<grid, 256>>>(Wo, att, bo, x,
                                              out, CCH * LSEQ, 0);
    }
}

// round 4
// speedup vs baseline: 3.6238x; 3.6222x over previous
#include <cuda_runtime.h>
#include <cstdint>

#define BATCH 8
#define LSEQ  1024
#define QK_SCALE 0.125f

// ---------------- scratch (no allocs allowed) ----------------
__device__ float g_hn [(size_t)BATCH*512*LSEQ];    // groupnorm out [b][c][L]
__device__ float g_qkv[(size_t)BATCH*1536*LSEQ];   // [b][row][L]: rows 0-511 q*s, 512-1023 k*s, 1024-1535 v
__device__ float g_att[(size_t)BATCH*512*LSEQ];    // attention out [b][inner][L]

// ---------------- helpers ----------------
__device__ __forceinline__ uint32_t f2tf(float f){
    uint32_t r; asm("cvt.rna.tf32.f32 %0, %1;" : "=r"(r) : "f"(f)); return r;
}
__device__ __forceinline__ void mma8(float* d, const uint32_t* a, uint32_t b0, uint32_t b1){
    asm volatile("mma.sync.aligned.m16n8k8.row.col.f32.tf32.tf32.f32 "
        "{%0,%1,%2,%3}, {%4,%5,%6,%7}, {%8,%9}, {%0,%1,%2,%3};"
        : "+f"(d[0]),"+f"(d[1]),"+f"(d[2]),"+f"(d[3])
        : "r"(a[0]),"r"(a[1]),"r"(a[2]),"r"(a[3]), "r"(b0),"r"(b1));
}

// ---------------- 1) GroupNorm -> hn[b][c][L] ----------------
__global__ __launch_bounds__(256) void gn_kernel(const float* __restrict__ x,
    const float* __restrict__ gamma, const float* __restrict__ beta, float* __restrict__ hn)
{
    const int b = blockIdx.x >> 5, g = blockIdx.x & 31;
    const float* xp = x  + ((size_t)b * 512 + g * 16) * LSEQ;
    float*       hp = hn + ((size_t)b * 512 + g * 16) * LSEQ;
    float s1 = 0.f, s2 = 0.f;
    for (int e = threadIdx.x; e < 16 * LSEQ; e += 256) { float v = xp[e]; s1 += v; s2 += v * v; }
    __shared__ float r1[32], r2[32];
    #pragma unroll
    for (int o = 16; o > 0; o >>= 1) {
        s1 += __shfl_down_sync(~0u, s1, o); s2 += __shfl_down_sync(~0u, s2, o);
    }
    int wid = threadIdx.x >> 5, lid = threadIdx.x & 31;
    if (lid == 0) { r1[wid] = s1; r2[wid] = s2; }
    __syncthreads();
    if (wid == 0) {
        s1 = (lid < 8) ? r1[lid] : 0.f; s2 = (lid < 8) ? r2[lid] : 0.f;
        #pragma unroll
        for (int o = 4; o > 0; o >>= 1) {
            s1 += __shfl_down_sync(~0u, s1, o); s2 += __shfl_down_sync(~0u, s2, o);
        }
        if (lid == 0) { r1[0] = s1; r2[0] = s2; }
    }
    __syncthreads();
    const float mean = r1[0] * (1.f / 16384.f);
    const float rstd = rsqrtf(r2[0] * (1.f / 16384.f) - mean * mean + 1e-5f);
    for (int e = threadIdx.x; e < 16 * LSEQ; e += 256) {
        int c = g * 16 + (e >> 10);
        hp[e] = (xp[e] - mean) * rstd * gamma[c] + beta[c];
    }
}

// ---------------- 2/4) tf32 mma.sync GEMM ----------------
// C[b][m][n] = sum_k A[m][k] * B[b][k][n], B = [b][512][1024]
// MODE 0: fused QKV (A from Wq/Wkv by m0), scale rows m<1024 by 0.125, write g_qkv
// MODE 1: out-proj, + bias + residual x, write d_out
template<int MODE>
__global__ __launch_bounds__(256) void gemm_mma(
    const float* __restrict__ W0, const float* __restrict__ b0v,
    const float* __restrict__ W1, const float* __restrict__ b1v,
    const float* __restrict__ Bmat, const float* __restrict__ xres,
    float* __restrict__ Cout)
{
    __shared__ uint32_t As[32][132];
    __shared__ uint32_t Bs[32][132];

    const int tid = threadIdx.x, lane = tid & 31, wid = tid >> 5;
    const int wm = wid & 3, wn = wid >> 2;
    const int n0 = blockIdx.x * 128, m0 = blockIdx.y * 128, b = blockIdx.z;

    const float* A; const float* bias;
    if (MODE == 0 && m0 >= 512) { A = W1 + (size_t)(m0 - 512) * 512; bias = b1v + (m0 - 512); }
    else                        { A = W0 + (size_t)m0 * 512;          bias = b0v + m0; }
    const float* Bb = Bmat + (size_t)b * 512 * 1024 + n0;

    float acc[2][8][4];
    #pragma unroll
    for (int mt = 0; mt < 2; mt++)
        #pragma unroll
        for (int nt = 0; nt < 8; nt++)
            #pragma unroll
            for (int r = 0; r < 4; r++) acc[mt][nt][r] = 0.f;

    for (int kc = 0; kc < 512; kc += 32) {
        #pragma unroll
        for (int it = 0; it < 4; it++) {
            int idx = tid + it * 256, r = idx >> 3, f = idx & 7;
            float4 v = *(const float4*)(A + (size_t)r * 512 + kc + f * 4);
            As[f*4+0][r] = f2tf(v.x); As[f*4+1][r] = f2tf(v.y);
            As[f*4+2][r] = f2tf(v.z); As[f*4+3][r] = f2tf(v.w);
        }
        #pragma unroll
        for (int it = 0; it < 4; it++) {
            int idx = tid + it * 256, k = idx >> 5, n4 = idx & 31;
            float4 v = *(const float4*)(Bb + (size_t)(kc + k) * 1024 + n4 * 4);
            uint4 w = make_uint4(f2tf(v.x), f2tf(v.y), f2tf(v.z), f2tf(v.w));
            *(uint4*)&Bs[k][n4 * 4] = w;
        }
        __syncthreads();
        #pragma unroll
        for (int ks = 0; ks < 4; ks++) {
            const int kl = ks * 8 + (lane & 3);
            uint32_t a[2][4];
            #pragma unroll
            for (int mt = 0; mt < 2; mt++) {
                const int rm = wm * 32 + mt * 16 + (lane >> 2);
                a[mt][0] = As[kl][rm];     a[mt][1] = As[kl][rm + 8];
                a[mt][2] = As[kl+4][rm];   a[mt][3] = As[kl+4][rm + 8];
            }
            #pragma unroll
            for (int nt = 0; nt < 8; nt++) {
                const int nb = wn * 64 + nt * 8 + (lane >> 2);
                uint32_t b0 = Bs[kl][nb], b1 = Bs[kl+4][nb];
                mma8(acc[0][nt], a[0], b0, b1);
                mma8(acc[1][nt], a[1], b0, b1);
            }
        }
        __syncthreads();
    }

    const float sc = (MODE == 0 && m0 < 1024) ? QK_SCALE : 1.0f;
    #pragma unroll
    for (int mt = 0; mt < 2; mt++) {
        const int loc = wm * 32 + mt * 16 + (lane >> 2);
        const int m = m0 + loc;
        const float bi0 = bias[loc], bi1 = bias[loc + 8];
        float* row0; float* row1; const float* xr0 = nullptr; const float* xr1 = nullptr;
        if (MODE == 0) {
            row0 = Cout + ((size_t)b * 1536 + m) * 1024 + n0;
            row1 = row0 + 8 * 1024;
        } else {
            row0 = Cout + ((size_t)b * 512 + m) * 1024 + n0;
            row1 = row0 + 8 * 1024;
            xr0 = xres + ((size_t)b * 512 + m) * 1024 + n0;
            xr1 = xr0 + 8 * 1024;
        }
        #pragma unroll
        for (int nt = 0; nt < 8; nt++) {
            const int nc = wn * 64 + nt * 8 + 2 * (lane & 3);
            float2 lo = make_float2((acc[mt][nt][0] + bi0) * sc, (acc[mt][nt][1] + bi0) * sc);
            float2 hi = make_float2((acc[mt][nt][2] + bi1) * sc, (acc[mt][nt][3] + bi1) * sc);
            if (MODE == 1) {
                float2 x0 = *(const float2*)(xr0 + nc);
                float2 x1 = *(const float2*)(xr1 + nc);
                lo.x += x0.x; lo.y += x0.y; hi.x += x1.x; hi.y += x1.y;
            }
            *(float2*)(row0 + nc) = lo;
            *(float2*)(row1 + nc) = hi;
        }
    }
}

// ---------------- 3) tf32 mma.sync flash attention (no max-sub: |S| < 0.2) ----------------
__global__ __launch_bounds__(256) void attn_mma(const float* __restrict__ qkv,
                                               float* __restrict__ att)
{
    extern __shared__ uint32_t dsm[];
    uint32_t (*Qs)[132] = (uint32_t(*)[132])dsm;
    uint32_t (*Ks)[132] = (uint32_t(*)[132])(dsm + 64 * 132);
    uint32_t (*Vs)[132] = (uint32_t(*)[132])(dsm + 2 * 64 * 132);
    uint32_t (*Ps)[132] = (uint32_t(*)[132])(dsm + 3 * 64 * 132);
    float* rs = (float*)(dsm + 3 * 64 * 132 + 128 * 132);

    const int tid = threadIdx.x, lane = tid & 31, wid = tid >> 5;
    const int wm = wid & 3, wn = wid >> 2;
    const int b = blockIdx.z, h = blockIdx.y, q0 = blockIdx.x * 128;

    const float* Qg = qkv + ((size_t)b * 1536 + h * 64) * 1024 + q0;
    const float* Kg = qkv + ((size_t)b * 1536 + 512 + h * 64) * 1024;
    const float* Vg = qkv + ((size_t)b * 1536 + 1024 + h * 64) * 1024;

    // load Q tile [d][t], tf32
    #pragma unroll
    for (int it = 0; it < 8; it++) {
        int idx = tid + it * 256, d = idx >> 5, t4 = (idx & 31) * 4;
        float4 v = *(const float4*)(Qg + (size_t)d * 1024 + t4);
        uint4 w = make_uint4(f2tf(v.x), f2tf(v.y), f2tf(v.z), f2tf(v.w));
        *(uint4*)&Qs[d][t4] = w;
    }
    if (tid < 128) rs[tid] = 0.f;

    float o_acc[2][4][4];
    #pragma unroll
    for (int mt = 0; mt < 2; mt++)
        #pragma unroll
        for (int nt = 0; nt < 4; nt++)
            #pragma unroll
            for (int r = 0; r < 4; r++) o_acc[mt][nt][r] = 0.f;

    for (int scnk = 0; scnk < 8; scnk++) {
        const int s0 = scnk * 128;
        __syncthreads();   // previous PV done; Q/rs ready on first iter
        #pragma unroll
        for (int it = 0; it < 8; it++) {
            int idx = tid + it * 256, d = idx >> 5, t4 = (idx & 31) * 4;
            float4 v = *(const float4*)(Kg + (size_t)d * 1024 + s0 + t4);
            *(uint4*)&Ks[d][t4] = make_uint4(f2tf(v.x), f2tf(v.y), f2tf(v.z), f2tf(v.w));
            float4 u = *(const float4*)(Vg + (size_t)d * 1024 + s0 + t4);
            *(uint4*)&Vs[d][t4] = make_uint4(f2tf(u.x), f2tf(u.y), f2tf(u.z), f2tf(u.w));
        }
        __syncthreads();

        // S = Q^T K  (m = t, n = s, k = d)
        float s_acc[2][8][4];
        #pragma unroll
        for (int mt = 0; mt < 2; mt++)
            #pragma unroll
            for (int nt = 0; nt < 8; nt++)
                #pragma unroll
                for (int r = 0; r < 4; r++) s_acc[mt][nt][r] = 0.f;

        #pragma unroll
        for (int ks = 0; ks < 8; ks++) {
            const int kl = ks * 8 + (lane & 3);
            uint32_t a[2][4];
            #pragma unroll
            for (int mt = 0; mt < 2; mt++) {
                const int rm = wm * 32 + mt * 16 + (lane >> 2);
                a[mt][0] = Qs[kl][rm];   a[mt][1] = Qs[kl][rm + 8];
                a[mt][2] = Qs[kl+4][rm]; a[mt][3] = Qs[kl+4][rm + 8];
            }
            #pragma unroll
            for (int nt = 0; nt < 8; nt++) {
                const int nb = wn * 64 + nt * 8 + (lane >> 2);
                uint32_t b0 = Ks[kl][nb], b1 = Ks[kl+4][nb];
                mma8(s_acc[0][nt], a[0], b0, b1);
                mma8(s_acc[1][nt], a[1], b0, b1);
            }
        }

        // exp + row sums + write P
        #pragma unroll
        for (int mt = 0; mt < 2; mt++) {
            const int rm = wm * 32 + mt * 16 + (lane >> 2);
            float slo = 0.f, shi = 0.f;
            #pragma unroll
            for (int nt = 0; nt < 8; nt++) {
                const int sc2 = wn * 64 + nt * 8 + 2 * (lane & 3);
                float e0 = __expf(s_acc[mt][nt][0]);
                float e1 = __expf(s_acc[mt][nt][1]);
                float e2 = __expf(s_acc[mt][nt][2]);
                float e3 = __expf(s_acc[mt][nt][3]);
                slo += e0 + e1; shi += e2 + e3;
                Ps[rm][sc2] = f2tf(e0);     Ps[rm][sc2 + 1] = f2tf(e1);
                Ps[rm + 8][sc2] = f2tf(e2); Ps[rm + 8][sc2 + 1] = f2tf(e3);
            }
            slo += __shfl_xor_sync(~0u, slo, 1); slo += __shfl_xor_sync(~0u, slo, 2);
            shi += __shfl_xor_sync(~0u, shi, 1); shi += __shfl_xor_sync(~0u, shi, 2);
            if ((lane & 3) == 0) {
                atomicAdd(&rs[rm], slo);
                atomicAdd(&rs[rm + 8], shi);
            }
        }
        __syncthreads();

        // O += P V^T  (m = t, n = d, k = s)
        #pragma unroll
        for (int ks = 0; ks < 16; ks++) {
            const int kl = ks * 8 + (lane & 3);
            uint32_t a[2][4];
            #pragma unroll
            for (int mt = 0; mt < 2; mt++) {
                const int rm = wm * 32 + mt * 16 + (lane >> 2);
                a[mt][0] = Ps[rm][kl];     a[mt][1] = Ps[rm + 8][kl];
                a[mt][2] = Ps[rm][kl + 4]; a[mt][3] = Ps[rm + 8][kl + 4];
            }
            #pragma unroll
            for (int nt = 0; nt < 4; nt++) {
                const int nb = wn * 32 + nt * 8 + (lane >> 2);
                uint32_t b0 = Vs[nb][kl], b1 = Vs[nb][kl + 4];
                mma8(o_acc[0][nt], a[0], b0, b1);
                mma8(o_acc[1][nt], a[1], b0, b1);
            }
        }
    }
    __syncthreads();

    // normalize + transpose via smem (reuse Ps as [d][t] float) + coalesced store
    float* Osm = (float*)Ps;
    #pragma unroll
    for (int mt = 0; mt < 2; mt++) {
        const int rm = wm * 32 + mt * 16 + (lane >> 2);
        const float ilo = 1.f / rs[rm], ihi = 1.f / rs[rm + 8];
        #pragma unroll
        for (int nt = 0; nt < 4; nt++) {
            const int d = wn * 32 + nt * 8 + 2 * (lane & 3);
            Osm[(size_t)d * 132 + rm]           = o_acc[mt][nt][0] * ilo;
            Osm[(size_t)(d + 1) * 132 + rm]     = o_acc[mt][nt][1] * ilo;
            Osm[(size_t)d * 132 + rm + 8]       = o_acc[mt][nt][2] * ihi;
            Osm[(size_t)(d + 1) * 132 + rm + 8] = o_acc[mt][nt][3] * ihi;
        }
    }
    __syncthreads();
    float* Og = att + ((size_t)b * 512 + h * 64) * 1024 + q0;
    #pragma unroll
    for (int it = 0; it < 8; it++) {
        int idx = tid + it * 256, d = idx >> 5, t4 = (idx & 31) * 4;
        *(float4*)(Og + (size_t)d * 1024 + t4) = *(float4*)&Osm[(size_t)d * 132 + t4];
    }
}

// ---------------- launch ----------------
extern "C" void kernel_launch(void* const* d_in, const int* in_sizes, int n_in,
                              void* d_out, int out_size)
{
    const float* x     = (const float*)d_in[0];
    const float* gamma = (const float*)d_in[1];
    const float* beta  = (const float*)d_in[2];
    const float* Wq    = (const float*)d_in[3];
    const float* bq    = (const float*)d_in[4];
    const float* Wkv   = (const float*)d_in[5];
    const float* bkv   = (const float*)d_in[6];
    const float* Wo    = (const float*)d_in[7];
    const float* bo    = (const float*)d_in[8];
    float* out = (float*)d_out;

    float* hn;  cudaGetSymbolAddress((void**)&hn,  g_hn);
    float* qkv; cudaGetSymbolAddress((void**)&qkv, g_qkv);
    float* att; cudaGetSymbolAddress((void**)&att, g_att);

    gn_kernel<<<256, 256>>>(x, gamma, beta, hn);

    {   // fused QKV projection
        dim3 grid(8, 12, BATCH);
        gemm_mma<0><<<grid, 256>>>(Wq, bq, Wkv, bkv, hn, nullptr, qkv);
    }
    {   // attention
        const int smem = (3 * 64 * 132 + 128 * 132 + 128) * 4;
        cudaFuncSetAttribute(attn_mma, cudaFuncAttributeMaxDynamicSharedMemorySize, smem);
        dim3 grid(8, 8, BATCH);
        attn_mma<<<grid, 256, smem>>>(qkv, att);
    }
    {   // output projection + residual
        dim3 grid(8, 4, BATCH);
        gemm_mma<1><<<grid, 256>>>(Wo, bo, nullptr, nullptr, att, x, out);
    }
}

// round 5
// speedup vs baseline: 6.4016x; 1.7665x over previous
#include <cuda_runtime.h>
#include <cuda_bf16.h>
#include <cstdint>

#define BATCH 8
#define LSEQ  1024
#define QK_SCALE 0.125f

// ---------------- scratch (no allocs allowed) ----------------
__device__ __nv_bfloat16 g_hn [(size_t)BATCH*512*LSEQ];    // [b][c][L]
__device__ __nv_bfloat16 g_qkv[(size_t)BATCH*1536*LSEQ];   // rows 0-511 q*s, 512-1023 k*s, 1024-1535 v
__device__ __nv_bfloat16 g_att[(size_t)BATCH*512*LSEQ];    // [b][inner][L]

// ---------------- helpers ----------------
__device__ __forceinline__ uint32_t s2u(const void* p){
    uint32_t a;
    asm("{ .reg .u64 t; cvta.to.shared.u64 t, %1; cvt.u32.u64 %0, t; }" : "=r"(a) : "l"(p));
    return a;
}
__device__ __forceinline__ void ldm4(uint32_t* r, uint32_t a){
    asm volatile("ldmatrix.sync.aligned.m8n8.x4.shared.b16 {%0,%1,%2,%3}, [%4];"
        : "=r"(r[0]),"=r"(r[1]),"=r"(r[2]),"=r"(r[3]) : "r"(a));
}
__device__ __forceinline__ void ldm4t(uint32_t* r, uint32_t a){
    asm volatile("ldmatrix.sync.aligned.m8n8.x4.trans.shared.b16 {%0,%1,%2,%3}, [%4];"
        : "=r"(r[0]),"=r"(r[1]),"=r"(r[2]),"=r"(r[3]) : "r"(a));
}
__device__ __forceinline__ void mma16(float* d, const uint32_t* a, uint32_t b0, uint32_t b1){
    asm volatile("mma.sync.aligned.m16n8k16.row.col.f32.bf16.bf16.f32 "
        "{%0,%1,%2,%3}, {%4,%5,%6,%7}, {%8,%9}, {%0,%1,%2,%3};"
        : "+f"(d[0]),"+f"(d[1]),"+f"(d[2]),"+f"(d[3])
        : "r"(a[0]),"r"(a[1]),"r"(a[2]),"r"(a[3]), "r"(b0),"r"(b1));
}
__device__ __forceinline__ uint32_t bfp(float x, float y){
    __nv_bfloat162 t = __floats2bfloat162_rn(x, y);
    return *(uint32_t*)&t;
}

// ---------------- 1) GroupNorm -> bf16 hn[b][c][L] ----------------
__global__ __launch_bounds__(256) void gn_kernel(const float* __restrict__ x,
    const float* __restrict__ gamma, const float* __restrict__ beta,
    __nv_bfloat16* __restrict__ hn)
{
    const int b = blockIdx.x >> 5, g = blockIdx.x & 31;
    const float* xp = x + ((size_t)b * 512 + g * 16) * LSEQ;
    __nv_bfloat16* hp = hn + ((size_t)b * 512 + g * 16) * LSEQ;
    float s1 = 0.f, s2 = 0.f;
    for (int e = threadIdx.x; e < 16 * LSEQ; e += 256) { float v = xp[e]; s1 += v; s2 += v * v; }
    __shared__ float r1[32], r2[32];
    #pragma unroll
    for (int o = 16; o > 0; o >>= 1) {
        s1 += __shfl_down_sync(~0u, s1, o); s2 += __shfl_down_sync(~0u, s2, o);
    }
    int wid = threadIdx.x >> 5, lid = threadIdx.x & 31;
    if (lid == 0) { r1[wid] = s1; r2[wid] = s2; }
    __syncthreads();
    if (wid == 0) {
        s1 = (lid < 8) ? r1[lid] : 0.f; s2 = (lid < 8) ? r2[lid] : 0.f;
        #pragma unroll
        for (int o = 4; o > 0; o >>= 1) {
            s1 += __shfl_down_sync(~0u, s1, o); s2 += __shfl_down_sync(~0u, s2, o);
        }
        if (lid == 0) { r1[0] = s1; r2[0] = s2; }
    }
    __syncthreads();
    const float mean = r1[0] * (1.f / 16384.f);
    const float rstd = rsqrtf(r2[0] * (1.f / 16384.f) - mean * mean + 1e-5f);
    for (int e = threadIdx.x * 2; e < 16 * LSEQ; e += 512) {
        int c = g * 16 + (e >> 10);
        float ga = gamma[c] * rstd, be = beta[c] - mean * ga;
        *(uint32_t*)(hp + e) = bfp(xp[e] * ga + be, xp[e + 1] * ga + be);
    }
}

// ---------------- 2/4) bf16 mma.sync GEMM (ldmatrix + reg-prefetch) ----------------
// C[b][m][n] = sum_k A[m][k]*B[b][k][n]; A fp32 weights, B bf16 [b][512][1024]
// MODE 0: fused QKV (scale m<1024 rows by 0.125), write bf16 g_qkv
// MODE 1: out-proj + bias + fp32 residual -> fp32 d_out
template<int MODE>
__global__ __launch_bounds__(256) void gemm_mma(
    const float* __restrict__ W0, const float* __restrict__ b0v,
    const float* __restrict__ W1, const float* __restrict__ b1v,
    const __nv_bfloat16* __restrict__ Bg, const float* __restrict__ xres,
    void* __restrict__ Cout)
{
    __shared__ __nv_bfloat16 As[128][40];    // [m][k] pad-> conflict-free ldmatrix
    __shared__ __nv_bfloat16 Bs[32][136];    // [k][n]

    const int tid = threadIdx.x, lane = tid & 31, wid = tid >> 5;
    const int wm = wid & 3, wn = wid >> 2;
    const int n0 = blockIdx.x * 128, m0 = blockIdx.y * 128, b = blockIdx.z;

    const float* A; const float* bias;
    if (MODE == 0 && m0 >= 512) { A = W1 + (size_t)(m0 - 512) * 512; bias = b1v + (m0 - 512); }
    else                        { A = W0 + (size_t)m0 * 512;          bias = b0v + m0; }
    const __nv_bfloat16* Bb = Bg + (size_t)b * 512 * 1024 + n0;

    const int ar = tid >> 1, akk = (tid & 1) * 16;

    float acc[2][8][4];
    #pragma unroll
    for (int mt = 0; mt < 2; mt++)
        #pragma unroll
        for (int nt = 0; nt < 8; nt++)
            #pragma unroll
            for (int r = 0; r < 4; r++) acc[mt][nt][r] = 0.f;

    float4 aR[4]; uint4 bR[2];
    {   const float* ap = A + (size_t)ar * 512 + akk;
        aR[0] = *(const float4*)(ap);     aR[1] = *(const float4*)(ap + 4);
        aR[2] = *(const float4*)(ap + 8); aR[3] = *(const float4*)(ap + 12);
        #pragma unroll
        for (int j = 0; j < 2; j++) {
            int e = tid * 2 + j;
            bR[j] = *(const uint4*)(Bb + (size_t)(e >> 4) * 1024 + (e & 15) * 8);
        }
    }

    for (int kc = 0; kc < 512; kc += 32) {
        *(uint4*)&As[ar][akk]     = make_uint4(bfp(aR[0].x,aR[0].y), bfp(aR[0].z,aR[0].w),
                                               bfp(aR[1].x,aR[1].y), bfp(aR[1].z,aR[1].w));
        *(uint4*)&As[ar][akk + 8] = make_uint4(bfp(aR[2].x,aR[2].y), bfp(aR[2].z,aR[2].w),
                                               bfp(aR[3].x,aR[3].y), bfp(aR[3].z,aR[3].w));
        #pragma unroll
        for (int j = 0; j < 2; j++) {
            int e = tid * 2 + j;
            *(uint4*)&Bs[e >> 4][(e & 15) * 8] = bR[j];
        }
        __syncthreads();
        if (kc + 32 < 512) {
            const float* ap = A + (size_t)ar * 512 + kc + 32 + akk;
            aR[0] = *(const float4*)(ap);     aR[1] = *(const float4*)(ap + 4);
            aR[2] = *(const float4*)(ap + 8); aR[3] = *(const float4*)(ap + 12);
            #pragma unroll
            for (int j = 0; j < 2; j++) {
                int e = tid * 2 + j;
                bR[j] = *(const uint4*)(Bb + (size_t)(kc + 32 + (e >> 4)) * 1024 + (e & 15) * 8);
            }
        }
        #pragma unroll
        for (int ks = 0; ks < 2; ks++) {
            const int kk = ks * 16;
            uint32_t af[2][4];
            #pragma unroll
            for (int mt = 0; mt < 2; mt++)
                ldm4(af[mt], s2u(&As[wm*32 + mt*16 + ((lane>>3)&1)*8 + (lane&7)][kk + (lane>>4)*8]));
            uint32_t bf_[4][4];
            #pragma unroll
            for (int j4 = 0; j4 < 4; j4++)
                ldm4t(bf_[j4], s2u(&Bs[kk + ((lane>>3)&1)*8 + (lane&7)][wn*64 + j4*16 + (lane>>4)*8]));
            #pragma unroll
            for (int nt = 0; nt < 8; nt++) {
                uint32_t b0 = bf_[nt>>1][(nt&1)*2], b1 = bf_[nt>>1][(nt&1)*2 + 1];
                mma16(acc[0][nt], af[0], b0, b1);
                mma16(acc[1][nt], af[1], b0, b1);
            }
        }
        __syncthreads();
    }

    const float sc = (MODE == 0 && m0 < 1024) ? QK_SCALE : 1.0f;
    #pragma unroll
    for (int mt = 0; mt < 2; mt++) {
        const int loc = wm * 32 + mt * 16 + (lane >> 2);
        const int m = m0 + loc;
        const float bi0 = bias[loc], bi1 = bias[loc + 8];
        #pragma unroll
        for (int nt = 0; nt < 8; nt++) {
            const int nc = wn * 64 + nt * 8 + 2 * (lane & 3);
            float v00 = (acc[mt][nt][0] + bi0) * sc, v01 = (acc[mt][nt][1] + bi0) * sc;
            float v10 = (acc[mt][nt][2] + bi1) * sc, v11 = (acc[mt][nt][3] + bi1) * sc;
            if (MODE == 0) {
                __nv_bfloat16* row0 = (__nv_bfloat16*)Cout + ((size_t)b * 1536 + m) * 1024 + n0 + nc;
                *(uint32_t*)row0              = bfp(v00, v01);
                *(uint32_t*)(row0 + 8 * 1024) = bfp(v10, v11);
            } else {
                float* row0 = (float*)Cout + ((size_t)b * 512 + m) * 1024 + n0 + nc;
                const float* xr0 = xres + ((size_t)b * 512 + m) * 1024 + n0 + nc;
                float2 x0 = *(const float2*)xr0, x1 = *(const float2*)(xr0 + 8 * 1024);
                *(float2*)row0              = make_float2(v00 + x0.x, v01 + x0.y);
                *(float2*)(row0 + 8 * 1024) = make_float2(v10 + x1.x, v11 + x1.y);
            }
        }
    }
}

// ---------------- 3) bf16 mma.sync flash attention (no max-sub: |S| < 0.2) ----------------
__global__ __launch_bounds__(256) void attn_mma(const __nv_bfloat16* __restrict__ qkv,
                                               __nv_bfloat16* __restrict__ att)
{
    extern __shared__ unsigned char dsm[];
    __nv_bfloat16 (*Qs)[136] = (__nv_bfloat16(*)[136])(dsm);            // [d][t]
    __nv_bfloat16 (*Ks)[136] = (__nv_bfloat16(*)[136])(dsm + 17408);    // [d][s]
    __nv_bfloat16 (*Vs)[136] = (__nv_bfloat16(*)[136])(dsm + 34816);    // [d][s]
    __nv_bfloat16 (*Ps)[136] = (__nv_bfloat16(*)[136])(dsm + 52224);    // [t][s]
    float* rs = (float*)(dsm + 87040);

    const int tid = threadIdx.x, lane = tid & 31, wid = tid >> 5;
    const int wm = wid & 3, wn = wid >> 2;
    const int b = blockIdx.z, h = blockIdx.y, q0 = blockIdx.x * 128;

    const __nv_bfloat16* Qg = qkv + ((size_t)b * 1536 + h * 64) * 1024 + q0;
    const __nv_bfloat16* Kg = qkv + ((size_t)b * 1536 + 512 + h * 64) * 1024;
    const __nv_bfloat16* Vg = qkv + ((size_t)b * 1536 + 1024 + h * 64) * 1024;

    #pragma unroll
    for (int it = 0; it < 4; it++) {
        int idx = tid + it * 256, d = idx >> 4, c8 = (idx & 15) * 8;
        *(uint4*)&Qs[d][c8] = *(const uint4*)(Qg + (size_t)d * 1024 + c8);
    }
    if (tid < 128) rs[tid] = 0.f;

    float o_acc[2][4][4];
    #pragma unroll
    for (int mt = 0; mt < 2; mt++)
        #pragma unroll
        for (int nt = 0; nt < 4; nt++)
            #pragma unroll
            for (int r = 0; r < 4; r++) o_acc[mt][nt][r] = 0.f;

    for (int ck = 0; ck < 8; ck++) {
        const int s0 = ck * 128;
        __syncthreads();  // Q/rs ready (ck=0); prev PV done (ck>0)
        #pragma unroll
        for (int it = 0; it < 4; it++) {
            int idx = tid + it * 256, d = idx >> 4, c8 = (idx & 15) * 8;
            *(uint4*)&Ks[d][c8] = *(const uint4*)(Kg + (size_t)d * 1024 + s0 + c8);
            *(uint4*)&Vs[d][c8] = *(const uint4*)(Vg + (size_t)d * 1024 + s0 + c8);
        }
        __syncthreads();

        // S = Q^T K (m=t, n=s, k=d=64)
        float s_acc[2][8][4];
        #pragma unroll
        for (int mt = 0; mt < 2; mt++)
            #pragma unroll
            for (int nt = 0; nt < 8; nt++)
                #pragma unroll
                for (int r = 0; r < 4; r++) s_acc[mt][nt][r] = 0.f;
        #pragma unroll
        for (int ks = 0; ks < 4; ks++) {
            const int kk = ks * 16;
            uint32_t af[2][4];
            #pragma unroll
            for (int mt = 0; mt < 2; mt++)
                ldm4t(af[mt], s2u(&Qs[kk + (lane>>4)*8 + (lane&7)][wm*32 + mt*16 + ((lane>>3)&1)*8]));
            uint32_t kf[4][4];
            #pragma unroll
            for (int j4 = 0; j4 < 4; j4++)
                ldm4t(kf[j4], s2u(&Ks[kk + ((lane>>3)&1)*8 + (lane&7)][wn*64 + j4*16 + (lane>>4)*8]));
            #pragma unroll
            for (int nt = 0; nt < 8; nt++) {
                uint32_t b0 = kf[nt>>1][(nt&1)*2], b1 = kf[nt>>1][(nt&1)*2 + 1];
                mma16(s_acc[0][nt], af[0], b0, b1);
                mma16(s_acc[1][nt], af[1], b0, b1);
            }
        }

        // exp, row sums, P -> smem (bf16)
        #pragma unroll
        for (int mt = 0; mt < 2; mt++) {
            const int rm = wm * 32 + mt * 16 + (lane >> 2);
            float slo = 0.f, shi = 0.f;
            #pragma unroll
            for (int nt = 0; nt < 8; nt++) {
                const int sc2 = wn * 64 + nt * 8 + 2 * (lane & 3);
                float e0 = __expf(s_acc[mt][nt][0]);
                float e1 = __expf(s_acc[mt][nt][1]);
                float e2 = __expf(s_acc[mt][nt][2]);
                float e3 = __expf(s_acc[mt][nt][3]);
                slo += e0 + e1; shi += e2 + e3;
                *(uint32_t*)&Ps[rm][sc2]     = bfp(e0, e1);
                *(uint32_t*)&Ps[rm + 8][sc2] = bfp(e2, e3);
            }
            slo += __shfl_xor_sync(~0u, slo, 1); slo += __shfl_xor_sync(~0u, slo, 2);
            shi += __shfl_xor_sync(~0u, shi, 1); shi += __shfl_xor_sync(~0u, shi, 2);
            if ((lane & 3) == 0) { atomicAdd(&rs[rm], slo); atomicAdd(&rs[rm + 8], shi); }
        }
        __syncthreads();

        // O += P V^T (m=t, n=d=64, k=s=128)
        #pragma unroll
        for (int ks = 0; ks < 8; ks++) {
            const int kk = ks * 16;
            uint32_t pa[2][4];
            #pragma unroll
            for (int mt = 0; mt < 2; mt++)
                ldm4(pa[mt], s2u(&Ps[wm*32 + mt*16 + ((lane>>3)&1)*8 + (lane&7)][kk + (lane>>4)*8]));
            uint32_t vb[2][4];
            #pragma unroll
            for (int j = 0; j < 2; j++)
                ldm4(vb[j], s2u(&Vs[wn*32 + j*16 + (lane>>4)*8 + (lane&7)][kk + ((lane>>3)&1)*8]));
            #pragma unroll
            for (int nt = 0; nt < 4; nt++) {
                uint32_t b0 = vb[nt>>1][(nt&1)*2], b1 = vb[nt>>1][(nt&1)*2 + 1];
                mma16(o_acc[0][nt], pa[0], b0, b1);
                mma16(o_acc[1][nt], pa[1], b0, b1);
            }
        }
    }
    __syncthreads();

    // normalize + transpose via smem (reuse Ps as float [64][136]) + bf16 store
    float* Osm = (float*)Ps;
    #pragma unroll
    for (int mt = 0; mt < 2; mt++) {
        const int rm = wm * 32 + mt * 16 + (lane >> 2);
        const float ilo = 1.f / rs[rm], ihi = 1.f / rs[rm + 8];
        #pragma unroll
        for (int nt = 0; nt < 4; nt++) {
            const int d = wn * 32 + nt * 8 + 2 * (lane & 3);
            Osm[(size_t)d * 136 + rm]           = o_acc[mt][nt][0] * ilo;
            Osm[(size_t)(d + 1) * 136 + rm]     = o_acc[mt][nt][1] * ilo;
            Osm[(size_t)d * 136 + rm + 8]       = o_acc[mt][nt][2] * ihi;
            Osm[(size_t)(d + 1) * 136 + rm + 8] = o_acc[mt][nt][3] * ihi;
        }
    }
    __syncthreads();
    __nv_bfloat16* Og = att + ((size_t)b * 512 + h * 64) * 1024 + q0;
    #pragma unroll
    for (int it = 0; it < 8; it++) {
        int idx = tid + it * 256, d = idx >> 5, t4 = (idx & 31) * 4;
        const float* src = &Osm[(size_t)d * 136 + t4];
        *(uint2*)(Og + (size_t)d * 1024 + t4) = make_uint2(bfp(src[0], src[1]), bfp(src[2], src[3]));
    }
}

// ---------------- launch ----------------
extern "C" void kernel_launch(void* const* d_in, const int* in_sizes, int n_in,
                              void* d_out, int out_size)
{
    const float* x     = (const float*)d_in[0];
    const float* gamma = (const float*)d_in[1];
    const float* beta  = (const float*)d_in[2];
    const float* Wq    = (const float*)d_in[3];
    const float* bq    = (const float*)d_in[4];
    const float* Wkv   = (const float*)d_in[5];
    const float* bkv   = (const float*)d_in[6];
    const float* Wo    = (const float*)d_in[7];
    const float* bo    = (const float*)d_in[8];

    __nv_bfloat16* hn;  cudaGetSymbolAddress((void**)&hn,  g_hn);
    __nv_bfloat16* qkv; cudaGetSymbolAddress((void**)&qkv, g_qkv);
    __nv_bfloat16* att; cudaGetSymbolAddress((void**)&att, g_att);

    gn_kernel<<<256, 256>>>(x, gamma, beta, hn);
    {
        dim3 grid(8, 12, BATCH);
        gemm_mma<0><<<grid, 256>>>(Wq, bq, Wkv, bkv, hn, nullptr, qkv);
    }
    {
        const int smem = 87552;
        cudaFuncSetAttribute(attn_mma, cudaFuncAttributeMaxDynamicSharedMemorySize, smem);
        dim3 grid(8, 8, BATCH);
        attn_mma<<<grid, 256, smem>>>(qkv, att);
    }
    {
        dim3 grid(8, 4, BATCH);
        gemm_mma<1><<<grid, 256>>>(Wo, bo, nullptr, nullptr, att, x, d_out ? (float*)d_out : nullptr);
    }
}

// round 6
// speedup vs baseline: 7.0941x; 1.1082x over previous
#include <cuda_runtime.h>
#include <cuda_bf16.h>
#include <cstdint>

#define BATCH 8
#define LSEQ  1024
#define QK_SCALE 0.125f

// ---------------- scratch (no allocs allowed) ----------------
__device__ __nv_bfloat16 g_hn [(size_t)BATCH*512*LSEQ];    // [b][c][L]
__device__ __nv_bfloat16 g_qkv[(size_t)BATCH*1536*LSEQ];   // rows 0-511 q*s, 512-1023 k*s, 1024-1535 v
__device__ __nv_bfloat16 g_att[(size_t)BATCH*512*LSEQ];    // [b][inner][L]
__device__ __nv_bfloat16 g_w  [(size_t)2048*512];          // bf16 weights: Wq | Wkv | Wo

// ---------------- helpers ----------------
__device__ __forceinline__ uint32_t s2u(const void* p){
    uint32_t a;
    asm("{ .reg .u64 t; cvta.to.shared.u64 t, %1; cvt.u32.u64 %0, t; }" : "=r"(a) : "l"(p));
    return a;
}
__device__ __forceinline__ void ldm4(uint32_t* r, uint32_t a){
    asm volatile("ldmatrix.sync.aligned.m8n8.x4.shared.b16 {%0,%1,%2,%3}, [%4];"
        : "=r"(r[0]),"=r"(r[1]),"=r"(r[2]),"=r"(r[3]) : "r"(a));
}
__device__ __forceinline__ void ldm4t(uint32_t* r, uint32_t a){
    asm volatile("ldmatrix.sync.aligned.m8n8.x4.trans.shared.b16 {%0,%1,%2,%3}, [%4];"
        : "=r"(r[0]),"=r"(r[1]),"=r"(r[2]),"=r"(r[3]) : "r"(a));
}
__device__ __forceinline__ void mma16(float* d, const uint32_t* a, uint32_t b0, uint32_t b1){
    asm volatile("mma.sync.aligned.m16n8k16.row.col.f32.bf16.bf16.f32 "
        "{%0,%1,%2,%3}, {%4,%5,%6,%7}, {%8,%9}, {%0,%1,%2,%3};"
        : "+f"(d[0]),"+f"(d[1]),"+f"(d[2]),"+f"(d[3])
        : "r"(a[0]),"r"(a[1]),"r"(a[2]),"r"(a[3]), "r"(b0),"r"(b1));
}
__device__ __forceinline__ uint32_t bfp(float x, float y){
    __nv_bfloat162 t = __floats2bfloat162_rn(x, y);
    return *(uint32_t*)&t;
}
#define CPA(s, g)   asm volatile("cp.async.cg.shared.global [%0], [%1], 16;" :: "r"(s2u(s)), "l"(g))
#define CPCOMMIT()  asm volatile("cp.async.commit_group;" ::: "memory")
#define CPWAIT0()   asm volatile("cp.async.wait_group 0;" ::: "memory")
#define CPWAIT1()   asm volatile("cp.async.wait_group 1;" ::: "memory")

// ---------------- 0) weight prep: fp32 -> bf16 ----------------
__global__ __launch_bounds__(256) void prep_kernel(const float* __restrict__ Wq,
    const float* __restrict__ Wkv, const float* __restrict__ Wo,
    __nv_bfloat16* __restrict__ w)
{
    const size_t off = ((size_t)blockIdx.x * 256 + threadIdx.x) * 4;
    const float* src;
    if (off < (size_t)512 * 512)            src = Wq + off;
    else if (off < (size_t)1536 * 512)      src = Wkv + (off - (size_t)512 * 512);
    else                                    src = Wo + (off - (size_t)1536 * 512);
    float4 v = *(const float4*)src;
    *(uint2*)(w + off) = make_uint2(bfp(v.x, v.y), bfp(v.z, v.w));
}

// ---------------- 1) GroupNorm -> bf16 hn[b][c][L] ----------------
__global__ __launch_bounds__(256) void gn_kernel(const float* __restrict__ x,
    const float* __restrict__ gamma, const float* __restrict__ beta,
    __nv_bfloat16* __restrict__ hn)
{
    const int b = blockIdx.x >> 5, g = blockIdx.x & 31;
    const float* xp = x + ((size_t)b * 512 + g * 16) * LSEQ;
    __nv_bfloat16* hp = hn + ((size_t)b * 512 + g * 16) * LSEQ;
    float s1 = 0.f, s2 = 0.f;
    for (int e = threadIdx.x; e < 16 * LSEQ; e += 256) { float v = xp[e]; s1 += v; s2 += v * v; }
    __shared__ float r1[32], r2[32];
    #pragma unroll
    for (int o = 16; o > 0; o >>= 1) {
        s1 += __shfl_down_sync(~0u, s1, o); s2 += __shfl_down_sync(~0u, s2, o);
    }
    int wid = threadIdx.x >> 5, lid = threadIdx.x & 31;
    if (lid == 0) { r1[wid] = s1; r2[wid] = s2; }
    __syncthreads();
    if (wid == 0) {
        s1 = (lid < 8) ? r1[lid] : 0.f; s2 = (lid < 8) ? r2[lid] : 0.f;
        #pragma unroll
        for (int o = 4; o > 0; o >>= 1) {
            s1 += __shfl_down_sync(~0u, s1, o); s2 += __shfl_down_sync(~0u, s2, o);
        }
        if (lid == 0) { r1[0] = s1; r2[0] = s2; }
    }
    __syncthreads();
    const float mean = r1[0] * (1.f / 16384.f);
    const float rstd = rsqrtf(r2[0] * (1.f / 16384.f) - mean * mean + 1e-5f);
    for (int e = threadIdx.x * 2; e < 16 * LSEQ; e += 512) {
        int c = g * 16 + (e >> 10);
        float ga = gamma[c] * rstd, be = beta[c] - mean * ga;
        *(uint32_t*)(hp + e) = bfp(xp[e] * ga + be, xp[e + 1] * ga + be);
    }
}

// ---------------- 2/4) bf16 GEMM, cp.async 2-stage pipeline ----------------
// C[b][m][n] = sum_k A[m][k]*B[b][k][n]; A bf16 from g_w, B bf16 [b][512][1024]
template<int MODE>
__global__ __launch_bounds__(256, 2) void gemm_mma(
    const __nv_bfloat16* __restrict__ Wall,
    const float* __restrict__ b0v, const float* __restrict__ b1v,
    const __nv_bfloat16* __restrict__ Bg, const float* __restrict__ xres,
    void* __restrict__ Cout)
{
    __shared__ __nv_bfloat16 As[2][128][40];
    __shared__ __nv_bfloat16 Bs[2][32][136];

    const int tid = threadIdx.x, lane = tid & 31, wid = tid >> 5;
    const int wm = wid & 3, wn = wid >> 2;
    const int n0 = blockIdx.x * 128, m0 = blockIdx.y * 128, b = blockIdx.z;

    const __nv_bfloat16* A;
    const float* bias;
    if (MODE == 0) {
        A = Wall + (size_t)m0 * 512;
        bias = (m0 < 512) ? (b0v + m0) : (b1v + (m0 - 512));
    } else {
        A = Wall + (size_t)(1536 + m0) * 512;
        bias = b0v + m0;
    }
    const __nv_bfloat16* Bb = Bg + (size_t)b * 512 * 1024 + n0;

    float acc[2][8][4];
    #pragma unroll
    for (int mt = 0; mt < 2; mt++)
        #pragma unroll
        for (int nt = 0; nt < 8; nt++)
            #pragma unroll
            for (int r = 0; r < 4; r++) acc[mt][nt][r] = 0.f;

    // stage fill: A 512 chunks + B 512 chunks, 4 cp.async/thread
    const int ae_r = tid >> 1, ae_c = (tid & 1) * 16;      // 2 chunks A (32B contiguous)
    const int be_k = tid >> 3, be_c = (tid & 7) * 16;      // 2 chunks B

    #define FILL(st, kc) do { \
        CPA(&As[st][ae_r][ae_c],     A + (size_t)ae_r * 512 + (kc) + ae_c); \
        CPA(&As[st][ae_r][ae_c + 8], A + (size_t)ae_r * 512 + (kc) + ae_c + 8); \
        CPA(&Bs[st][be_k][be_c],     Bb + (size_t)((kc) + be_k) * 1024 + be_c); \
        CPA(&Bs[st][be_k][be_c + 8], Bb + (size_t)((kc) + be_k) * 1024 + be_c + 8); \
        CPCOMMIT(); } while (0)

    FILL(0, 0);
    #pragma unroll 1
    for (int i = 0; i < 16; i++) {
        const int st = i & 1;
        if (i + 1 < 16) { FILL(st ^ 1, (i + 1) * 32); CPWAIT1(); }
        else            { CPWAIT0(); }
        __syncthreads();
        #pragma unroll
        for (int ks = 0; ks < 2; ks++) {
            const int kk = ks * 16;
            uint32_t af[2][4];
            #pragma unroll
            for (int mt = 0; mt < 2; mt++)
                ldm4(af[mt], s2u(&As[st][wm*32 + mt*16 + ((lane>>3)&1)*8 + (lane&7)][kk + (lane>>4)*8]));
            uint32_t bf_[4][4];
            #pragma unroll
            for (int j4 = 0; j4 < 4; j4++)
                ldm4t(bf_[j4], s2u(&Bs[st][kk + ((lane>>3)&1)*8 + (lane&7)][wn*64 + j4*16 + (lane>>4)*8]));
            #pragma unroll
            for (int nt = 0; nt < 8; nt++) {
                uint32_t b0 = bf_[nt>>1][(nt&1)*2], b1 = bf_[nt>>1][(nt&1)*2 + 1];
                mma16(acc[0][nt], af[0], b0, b1);
                mma16(acc[1][nt], af[1], b0, b1);
            }
        }
        __syncthreads();
    }

    const float sc = (MODE == 0 && m0 < 1024) ? QK_SCALE : 1.0f;
    #pragma unroll
    for (int mt = 0; mt < 2; mt++) {
        const int loc = wm * 32 + mt * 16 + (lane >> 2);
        const int m = m0 + loc;
        const float bi0 = bias[loc], bi1 = bias[loc + 8];
        #pragma unroll
        for (int nt = 0; nt < 8; nt++) {
            const int nc = wn * 64 + nt * 8 + 2 * (lane & 3);
            float v00 = (acc[mt][nt][0] + bi0) * sc, v01 = (acc[mt][nt][1] + bi0) * sc;
            float v10 = (acc[mt][nt][2] + bi1) * sc, v11 = (acc[mt][nt][3] + bi1) * sc;
            if (MODE == 0) {
                __nv_bfloat16* row0 = (__nv_bfloat16*)Cout + ((size_t)b * 1536 + m) * 1024 + n0 + nc;
                *(uint32_t*)row0              = bfp(v00, v01);
                *(uint32_t*)(row0 + 8 * 1024) = bfp(v10, v11);
            } else {
                float* row0 = (float*)Cout + ((size_t)b * 512 + m) * 1024 + n0 + nc;
                const float* xr0 = xres + ((size_t)b * 512 + m) * 1024 + n0 + nc;
                float2 x0 = *(const float2*)xr0, x1 = *(const float2*)(xr0 + 8 * 1024);
                *(float2*)row0              = make_float2(v00 + x0.x, v01 + x0.y);
                *(float2*)(row0 + 8 * 1024) = make_float2(v10 + x1.x, v11 + x1.y);
            }
        }
    }
    #undef FILL
}

// ---------------- 3) bf16 flash attention, cp.async K/V double buffer ----------------
__global__ __launch_bounds__(256) void attn_mma(const __nv_bfloat16* __restrict__ qkv,
                                               __nv_bfloat16* __restrict__ att)
{
    extern __shared__ unsigned char dsm[];
    __nv_bfloat16 (*Qs)[136]    = (__nv_bfloat16(*)[136])(dsm);                 // [64][136]
    __nv_bfloat16 (*Ks)[64][136]= (__nv_bfloat16(*)[64][136])(dsm + 17408);     // [2][64][136]
    __nv_bfloat16 (*Vs)[64][136]= (__nv_bfloat16(*)[64][136])(dsm + 52224);     // [2][64][136]
    __nv_bfloat16 (*Ps)[136]    = (__nv_bfloat16(*)[136])(dsm + 87040);         // [128][136]
    float* rs = (float*)(dsm + 121856);

    const int tid = threadIdx.x, lane = tid & 31, wid = tid >> 5;
    const int wm = wid & 3, wn = wid >> 2;
    const int b = blockIdx.z, h = blockIdx.y, q0 = blockIdx.x * 128;

    const __nv_bfloat16* Qg = qkv + ((size_t)b * 1536 + h * 64) * 1024 + q0;
    const __nv_bfloat16* Kg = qkv + ((size_t)b * 1536 + 512 + h * 64) * 1024;
    const __nv_bfloat16* Vg = qkv + ((size_t)b * 1536 + 1024 + h * 64) * 1024;

    const int fd = tid >> 2, fc = (tid & 3) * 32;   // 4 chunks K + 4 chunks V per thread
    #define FILLKV(st, s0) do { \
        _Pragma("unroll") \
        for (int j = 0; j < 4; j++) { \
            CPA(&Ks[st][fd][fc + j * 8], Kg + (size_t)fd * 1024 + (s0) + fc + j * 8); \
            CPA(&Vs[st][fd][fc + j * 8], Vg + (size_t)fd * 1024 + (s0) + fc + j * 8); } \
        CPCOMMIT(); } while (0)

    FILLKV(0, 0);
    #pragma unroll
    for (int it = 0; it < 4; it++) {
        int idx = tid + it * 256, d = idx >> 4, c8 = (idx & 15) * 8;
        *(uint4*)&Qs[d][c8] = *(const uint4*)(Qg + (size_t)d * 1024 + c8);
    }
    if (tid < 128) rs[tid] = 0.f;

    float o_acc[2][4][4];
    #pragma unroll
    for (int mt = 0; mt < 2; mt++)
        #pragma unroll
        for (int nt = 0; nt < 4; nt++)
            #pragma unroll
            for (int r = 0; r < 4; r++) o_acc[mt][nt][r] = 0.f;

    #pragma unroll 1
    for (int ck = 0; ck < 8; ck++) {
        const int st = ck & 1;
        if (ck + 1 < 8) { FILLKV(st ^ 1, (ck + 1) * 128); CPWAIT1(); }
        else            { CPWAIT0(); }
        __syncthreads();

        // S = Q^T K (m=t, n=s, k=d=64)
        float s_acc[2][8][4];
        #pragma unroll
        for (int mt = 0; mt < 2; mt++)
            #pragma unroll
            for (int nt = 0; nt < 8; nt++)
                #pragma unroll
                for (int r = 0; r < 4; r++) s_acc[mt][nt][r] = 0.f;
        #pragma unroll
        for (int ks = 0; ks < 4; ks++) {
            const int kk = ks * 16;
            uint32_t af[2][4];
            #pragma unroll
            for (int mt = 0; mt < 2; mt++)
                ldm4t(af[mt], s2u(&Qs[kk + (lane>>4)*8 + (lane&7)][wm*32 + mt*16 + ((lane>>3)&1)*8]));
            uint32_t kf[4][4];
            #pragma unroll
            for (int j4 = 0; j4 < 4; j4++)
                ldm4t(kf[j4], s2u(&Ks[st][kk + ((lane>>3)&1)*8 + (lane&7)][wn*64 + j4*16 + (lane>>4)*8]));
            #pragma unroll
            for (int nt = 0; nt < 8; nt++) {
                uint32_t b0 = kf[nt>>1][(nt&1)*2], b1 = kf[nt>>1][(nt&1)*2 + 1];
                mma16(s_acc[0][nt], af[0], b0, b1);
                mma16(s_acc[1][nt], af[1], b0, b1);
            }
        }

        // exp, row sums, P -> smem (bf16)
        #pragma unroll
        for (int mt = 0; mt < 2; mt++) {
            const int rm = wm * 32 + mt * 16 + (lane >> 2);
            float slo = 0.f, shi = 0.f;
            #pragma unroll
            for (int nt = 0; nt < 8; nt++) {
                const int sc2 = wn * 64 + nt * 8 + 2 * (lane & 3);
                float e0 = __expf(s_acc[mt][nt][0]);
                float e1 = __expf(s_acc[mt][nt][1]);
                float e2 = __expf(s_acc[mt][nt][2]);
                float e3 = __expf(s_acc[mt][nt][3]);
                slo += e0 + e1; shi += e2 + e3;
                *(uint32_t*)&Ps[rm][sc2]     = bfp(e0, e1);
                *(uint32_t*)&Ps[rm + 8][sc2] = bfp(e2, e3);
            }
            slo += __shfl_xor_sync(~0u, slo, 1); slo += __shfl_xor_sync(~0u, slo, 2);
            shi += __shfl_xor_sync(~0u, shi, 1); shi += __shfl_xor_sync(~0u, shi, 2);
            if ((lane & 3) == 0) { atomicAdd(&rs[rm], slo); atomicAdd(&rs[rm + 8], shi); }
        }
        __syncthreads();

        // O += P V^T (m=t, n=d=64, k=s=128)
        #pragma unroll
        for (int ks = 0; ks < 8; ks++) {
            const int kk = ks * 16;
            uint32_t pa[2][4];
            #pragma unroll
            for (int mt = 0; mt < 2; mt++)
                ldm4(pa[mt], s2u(&Ps[wm*32 + mt*16 + ((lane>>3)&1)*8 + (lane&7)][kk + (lane>>4)*8]));
            uint32_t vb[2][4];
            #pragma unroll
            for (int j = 0; j < 2; j++)
                ldm4(vb[j], s2u(&Vs[st][wn*32 + j*16 + (lane>>4)*8 + (lane&7)][kk + ((lane>>3)&1)*8]));
            #pragma unroll
            for (int nt = 0; nt < 4; nt++) {
                uint32_t b0 = vb[nt>>1][(nt&1)*2], b1 = vb[nt>>1][(nt&1)*2 + 1];
                mma16(o_acc[0][nt], pa[0], b0, b1);
                mma16(o_acc[1][nt], pa[1], b0, b1);
            }
        }
        __syncthreads();   // Vs/Ps free before next fill/exp
    }

    // normalize + transpose via smem (reuse Ps as float [64][136]) + bf16 store
    float* Osm = (float*)Ps;
    #pragma unroll
    for (int mt = 0; mt < 2; mt++) {
        const int rm = wm * 32 + mt * 16 + (lane >> 2);
        const float ilo = 1.f / rs[rm], ihi = 1.f / rs[rm + 8];
        #pragma unroll
        for (int nt = 0; nt < 4; nt++) {
            const int d = wn * 32 + nt * 8 + 2 * (lane & 3);
            Osm[(size_t)d * 136 + rm]           = o_acc[mt][nt][0] * ilo;
            Osm[(size_t)(d + 1) * 136 + rm]     = o_acc[mt][nt][1] * ilo;
            Osm[(size_t)d * 136 + rm + 8]       = o_acc[mt][nt][2] * ihi;
            Osm[(size_t)(d + 1) * 136 + rm + 8] = o_acc[mt][nt][3] * ihi;
        }
    }
    __syncthreads();
    __nv_bfloat16* Og = att + ((size_t)b * 512 + h * 64) * 1024 + q0;
    #pragma unroll
    for (int it = 0; it < 8; it++) {
        int idx = tid + it * 256, d = idx >> 5, t4 = (idx & 31) * 4;
        const float* src = &Osm[(size_t)d * 136 + t4];
        *(uint2*)(Og + (size_t)d * 1024 + t4) = make_uint2(bfp(src[0], src[1]), bfp(src[2], src[3]));
    }
    #undef FILLKV
}

// ---------------- launch ----------------
extern "C" void kernel_launch(void* const* d_in, const int* in_sizes, int n_in,
                              void* d_out, int out_size)
{
    const float* x     = (const float*)d_in[0];
    const float* gamma = (const float*)d_in[1];
    const float* beta  = (const float*)d_in[2];
    const float* Wq    = (const float*)d_in[3];
    const float* bq    = (const float*)d_in[4];
    const float* Wkv   = (const float*)d_in[5];
    const float* bkv   = (const float*)d_in[6];
    const float* Wo    = (const float*)d_in[7];
    const float* bo    = (const float*)d_in[8];

    __nv_bfloat16* hn;  cudaGetSymbolAddress((void**)&hn,  g_hn);
    __nv_bfloat16* qkv; cudaGetSymbolAddress((void**)&qkv, g_qkv);
    __nv_bfloat16* att; cudaGetSymbolAddress((void**)&att, g_att);
    __nv_bfloat16* w;   cudaGetSymbolAddress((void**)&w,   g_w);

    prep_kernel<<<1024, 256>>>(Wq, Wkv, Wo, w);
    gn_kernel<<<256, 256>>>(x, gamma, beta, hn);
    {
        dim3 grid(8, 12, BATCH);
        gemm_mma<0><<<grid, 256>>>(w, bq, bkv, hn, nullptr, qkv);
    }
    {
        const int smem = 122368;
        cudaFuncSetAttribute(attn_mma, cudaFuncAttributeMaxDynamicSharedMemorySize, smem);
        dim3 grid(8, 8, BATCH);
        attn_mma<<<grid, 256, smem>>>(qkv, att);
    }
    {
        dim3 grid(8, 4, BATCH);
        gemm_mma<1><<<grid, 256>>>(w, bo, nullptr, att, x, d_out);
    }
}

// round 7
// speedup vs baseline: 7.3823x; 1.0406x over previous
#include <cuda_runtime.h>
#include <cuda_bf16.h>
#include <cstdint>

#define BATCH 8
#define LSEQ  1024
#define QK_SCALE 0.125f

// ---------------- scratch (no allocs allowed) ----------------
__device__ __nv_bfloat16 g_hn [(size_t)BATCH*512*LSEQ];    // [b][c][L]
__device__ __nv_bfloat16 g_qkv[(size_t)BATCH*1536*LSEQ];   // rows 0-511 q*s, 512-1023 k*s, 1024-1535 v
__device__ __nv_bfloat16 g_att[(size_t)BATCH*512*LSEQ];    // [b][inner][L]
__device__ __nv_bfloat16 g_w  [(size_t)2048*512];          // bf16 weights: Wq | Wkv | Wo

// ---------------- helpers ----------------
__device__ __forceinline__ uint32_t s2u(const void* p){
    uint32_t a;
    asm("{ .reg .u64 t; cvta.to.shared.u64 t, %1; cvt.u32.u64 %0, t; }" : "=r"(a) : "l"(p));
    return a;
}
__device__ __forceinline__ void ldm4(uint32_t* r, uint32_t a){
    asm volatile("ldmatrix.sync.aligned.m8n8.x4.shared.b16 {%0,%1,%2,%3}, [%4];"
        : "=r"(r[0]),"=r"(r[1]),"=r"(r[2]),"=r"(r[3]) : "r"(a));
}
__device__ __forceinline__ void ldm4t(uint32_t* r, uint32_t a){
    asm volatile("ldmatrix.sync.aligned.m8n8.x4.trans.shared.b16 {%0,%1,%2,%3}, [%4];"
        : "=r"(r[0]),"=r"(r[1]),"=r"(r[2]),"=r"(r[3]) : "r"(a));
}
__device__ __forceinline__ void mma16(float* d, const uint32_t* a, uint32_t b0, uint32_t b1){
    asm volatile("mma.sync.aligned.m16n8k16.row.col.f32.bf16.bf16.f32 "
        "{%0,%1,%2,%3}, {%4,%5,%6,%7}, {%8,%9}, {%0,%1,%2,%3};"
        : "+f"(d[0]),"+f"(d[1]),"+f"(d[2]),"+f"(d[3])
        : "r"(a[0]),"r"(a[1]),"r"(a[2]),"r"(a[3]), "r"(b0),"r"(b1));
}
__device__ __forceinline__ uint32_t bfp(float x, float y){
    __nv_bfloat162 t = __floats2bfloat162_rn(x, y);
    return *(uint32_t*)&t;
}
#define CPA(s, g)   asm volatile("cp.async.cg.shared.global [%0], [%1], 16;" :: "r"(s2u(s)), "l"(g))
#define CPCOMMIT()  asm volatile("cp.async.commit_group;" ::: "memory")
#define CPWAIT(n)   asm volatile("cp.async.wait_group %0;" :: "n"(n) : "memory")

// ---------------- 0) weight prep: fp32 -> bf16 ----------------
__global__ __launch_bounds__(256) void prep_kernel(const float* __restrict__ Wq,
    const float* __restrict__ Wkv, const float* __restrict__ Wo,
    __nv_bfloat16* __restrict__ w)
{
    const size_t off = ((size_t)blockIdx.x * 256 + threadIdx.x) * 4;
    const float* src;
    if (off < (size_t)512 * 512)            src = Wq + off;
    else if (off < (size_t)1536 * 512)      src = Wkv + (off - (size_t)512 * 512);
    else                                    src = Wo + (off - (size_t)1536 * 512);
    float4 v = *(const float4*)src;
    *(uint2*)(w + off) = make_uint2(bfp(v.x, v.y), bfp(v.z, v.w));
}

// ---------------- 1) GroupNorm -> bf16 hn[b][c][L] ----------------
__global__ __launch_bounds__(256) void gn_kernel(const float* __restrict__ x,
    const float* __restrict__ gamma, const float* __restrict__ beta,
    __nv_bfloat16* __restrict__ hn)
{
    const int b = blockIdx.x >> 5, g = blockIdx.x & 31;
    const float* xp = x + ((size_t)b * 512 + g * 16) * LSEQ;
    __nv_bfloat16* hp = hn + ((size_t)b * 512 + g * 16) * LSEQ;
    float s1 = 0.f, s2 = 0.f;
    for (int e = threadIdx.x * 4; e < 16 * LSEQ; e += 1024) {
        float4 v = *(const float4*)(xp + e);
        s1 += v.x + v.y + v.z + v.w;
        s2 += v.x * v.x + v.y * v.y + v.z * v.z + v.w * v.w;
    }
    __shared__ float r1[32], r2[32];
    #pragma unroll
    for (int o = 16; o > 0; o >>= 1) {
        s1 += __shfl_down_sync(~0u, s1, o); s2 += __shfl_down_sync(~0u, s2, o);
    }
    int wid = threadIdx.x >> 5, lid = threadIdx.x & 31;
    if (lid == 0) { r1[wid] = s1; r2[wid] = s2; }
    __syncthreads();
    if (wid == 0) {
        s1 = (lid < 8) ? r1[lid] : 0.f; s2 = (lid < 8) ? r2[lid] : 0.f;
        #pragma unroll
        for (int o = 4; o > 0; o >>= 1) {
            s1 += __shfl_down_sync(~0u, s1, o); s2 += __shfl_down_sync(~0u, s2, o);
        }
        if (lid == 0) { r1[0] = s1; r2[0] = s2; }
    }
    __syncthreads();
    const float mean = r1[0] * (1.f / 16384.f);
    const float rstd = rsqrtf(r2[0] * (1.f / 16384.f) - mean * mean + 1e-5f);
    for (int e = threadIdx.x * 4; e < 16 * LSEQ; e += 1024) {
        int c = g * 16 + (e >> 10);
        float ga = gamma[c] * rstd, be = beta[c] - mean * ga;
        float4 v = *(const float4*)(xp + e);
        *(uint2*)(hp + e) = make_uint2(bfp(v.x * ga + be, v.y * ga + be),
                                       bfp(v.z * ga + be, v.w * ga + be));
    }
}

// ---------------- 2/4) bf16 GEMM, cp.async 2-stage pipeline ----------------
template<int MODE>
__global__ __launch_bounds__(256, 2) void gemm_mma(
    const __nv_bfloat16* __restrict__ Wall,
    const float* __restrict__ b0v, const float* __restrict__ b1v,
    const __nv_bfloat16* __restrict__ Bg, const float* __restrict__ xres,
    void* __restrict__ Cout)
{
    __shared__ __nv_bfloat16 As[2][128][40];
    __shared__ __nv_bfloat16 Bs[2][32][136];

    const int tid = threadIdx.x, lane = tid & 31, wid = tid >> 5;
    const int wm = wid & 3, wn = wid >> 2;
    const int n0 = blockIdx.x * 128, m0 = blockIdx.y * 128, b = blockIdx.z;

    const __nv_bfloat16* A;
    const float* bias;
    if (MODE == 0) {
        A = Wall + (size_t)m0 * 512;
        bias = (m0 < 512) ? (b0v + m0) : (b1v + (m0 - 512));
    } else {
        A = Wall + (size_t)(1536 + m0) * 512;
        bias = b0v + m0;
    }
    const __nv_bfloat16* Bb = Bg + (size_t)b * 512 * 1024 + n0;

    float acc[2][8][4];
    #pragma unroll
    for (int mt = 0; mt < 2; mt++)
        #pragma unroll
        for (int nt = 0; nt < 8; nt++)
            #pragma unroll
            for (int r = 0; r < 4; r++) acc[mt][nt][r] = 0.f;

    const int ae_r = tid >> 1, ae_c = (tid & 1) * 16;
    const int be_k = tid >> 3, be_c = (tid & 7) * 16;

    #define FILL(st, kc) do { \
        CPA(&As[st][ae_r][ae_c],     A + (size_t)ae_r * 512 + (kc) + ae_c); \
        CPA(&As[st][ae_r][ae_c + 8], A + (size_t)ae_r * 512 + (kc) + ae_c + 8); \
        CPA(&Bs[st][be_k][be_c],     Bb + (size_t)((kc) + be_k) * 1024 + be_c); \
        CPA(&Bs[st][be_k][be_c + 8], Bb + (size_t)((kc) + be_k) * 1024 + be_c + 8); \
        CPCOMMIT(); } while (0)

    FILL(0, 0);
    #pragma unroll 1
    for (int i = 0; i < 16; i++) {
        const int st = i & 1;
        if (i + 1 < 16) { FILL(st ^ 1, (i + 1) * 32); CPWAIT(1); }
        else            { CPWAIT(0); }
        __syncthreads();
        #pragma unroll
        for (int ks = 0; ks < 2; ks++) {
            const int kk = ks * 16;
            uint32_t af[2][4];
            #pragma unroll
            for (int mt = 0; mt < 2; mt++)
                ldm4(af[mt], s2u(&As[st][wm*32 + mt*16 + ((lane>>3)&1)*8 + (lane&7)][kk + (lane>>4)*8]));
            uint32_t bf_[4][4];
            #pragma unroll
            for (int j4 = 0; j4 < 4; j4++)
                ldm4t(bf_[j4], s2u(&Bs[st][kk + ((lane>>3)&1)*8 + (lane&7)][wn*64 + j4*16 + (lane>>4)*8]));
            #pragma unroll
            for (int nt = 0; nt < 8; nt++) {
                uint32_t b0 = bf_[nt>>1][(nt&1)*2], b1 = bf_[nt>>1][(nt&1)*2 + 1];
                mma16(acc[0][nt], af[0], b0, b1);
                mma16(acc[1][nt], af[1], b0, b1);
            }
        }
        __syncthreads();
    }

    const float sc = (MODE == 0 && m0 < 1024) ? QK_SCALE : 1.0f;
    #pragma unroll
    for (int mt = 0; mt < 2; mt++) {
        const int loc = wm * 32 + mt * 16 + (lane >> 2);
        const int m = m0 + loc;
        const float bi0 = bias[loc], bi1 = bias[loc + 8];
        #pragma unroll
        for (int nt = 0; nt < 8; nt++) {
            const int nc = wn * 64 + nt * 8 + 2 * (lane & 3);
            float v00 = (acc[mt][nt][0] + bi0) * sc, v01 = (acc[mt][nt][1] + bi0) * sc;
            float v10 = (acc[mt][nt][2] + bi1) * sc, v11 = (acc[mt][nt][3] + bi1) * sc;
            if (MODE == 0) {
                __nv_bfloat16* row0 = (__nv_bfloat16*)Cout + ((size_t)b * 1536 + m) * 1024 + n0 + nc;
                *(uint32_t*)row0              = bfp(v00, v01);
                *(uint32_t*)(row0 + 8 * 1024) = bfp(v10, v11);
            } else {
                float* row0 = (float*)Cout + ((size_t)b * 512 + m) * 1024 + n0 + nc;
                const float* xr0 = xres + ((size_t)b * 512 + m) * 1024 + n0 + nc;
                float2 x0 = *(const float2*)xr0, x1 = *(const float2*)(xr0 + 8 * 1024);
                *(float2*)row0              = make_float2(v00 + x0.x, v01 + x0.y);
                *(float2*)(row0 + 8 * 1024) = make_float2(v10 + x1.x, v11 + x1.y);
            }
        }
    }
    #undef FILL
}

// ---------------- 3) bf16 flash attention, K double buffer + V single buffer ----------------
// smem: Qs 17408 | Ks 2x17408 | Vs 17408 | Ps 34816 | rs 512 = 104960 -> 2 CTAs/SM
__global__ __launch_bounds__(256, 2) void attn_mma(const __nv_bfloat16* __restrict__ qkv,
                                                   __nv_bfloat16* __restrict__ att)
{
    extern __shared__ unsigned char dsm[];
    __nv_bfloat16 (*Qs)[136]     = (__nv_bfloat16(*)[136])(dsm);              // [64][136]
    __nv_bfloat16 (*Ks)[64][136] = (__nv_bfloat16(*)[64][136])(dsm + 17408);  // [2][64][136]
    __nv_bfloat16 (*Vs)[136]     = (__nv_bfloat16(*)[136])(dsm + 52224);      // [64][136]
    __nv_bfloat16 (*Ps)[136]     = (__nv_bfloat16(*)[136])(dsm + 69632);      // [128][136]
    float* rs = (float*)(dsm + 104448);

    const int tid = threadIdx.x, lane = tid & 31, wid = tid >> 5;
    const int wm = wid & 3, wn = wid >> 2;
    const int b = blockIdx.z, h = blockIdx.y, q0 = blockIdx.x * 128;

    const __nv_bfloat16* Qg = qkv + ((size_t)b * 1536 + h * 64) * 1024 + q0;
    const __nv_bfloat16* Kg = qkv + ((size_t)b * 1536 + 512 + h * 64) * 1024;
    const __nv_bfloat16* Vg = qkv + ((size_t)b * 1536 + 1024 + h * 64) * 1024;

    const int fd = tid >> 2, fc = (tid & 3) * 32;
    #define FILLK(st, s0) do { \
        _Pragma("unroll") \
        for (int j = 0; j < 4; j++) \
            CPA(&Ks[st][fd][fc + j * 8], Kg + (size_t)fd * 1024 + (s0) + fc + j * 8); \
        CPCOMMIT(); } while (0)
    #define FILLV(s0) do { \
        _Pragma("unroll") \
        for (int j = 0; j < 4; j++) \
            CPA(&Vs[fd][fc + j * 8], Vg + (size_t)fd * 1024 + (s0) + fc + j * 8); \
        CPCOMMIT(); } while (0)

    FILLK(0, 0);
    #pragma unroll
    for (int it = 0; it < 4; it++) {
        int idx = tid + it * 256, d = idx >> 4, c8 = (idx & 15) * 8;
        *(uint4*)&Qs[d][c8] = *(const uint4*)(Qg + (size_t)d * 1024 + c8);
    }
    if (tid < 128) rs[tid] = 0.f;

    float o_acc[2][4][4];
    #pragma unroll
    for (int mt = 0; mt < 2; mt++)
        #pragma unroll
        for (int nt = 0; nt < 4; nt++)
            #pragma unroll
            for (int r = 0; r < 4; r++) o_acc[mt][nt][r] = 0.f;

    #pragma unroll 1
    for (int ck = 0; ck < 8; ck++) {
        const int st = ck & 1;
        FILLV(ck * 128);
        if (ck + 1 < 8) { FILLK(st ^ 1, (ck + 1) * 128); CPWAIT(2); }
        else            { CPWAIT(1); }
        __syncthreads();    // K(ck) visible; Vs overwrite safe (prev PV done via loop-end sync)

        // S = Q^T K (m=t, n=s, k=d=64)
        float s_acc[2][8][4];
        #pragma unroll
        for (int mt = 0; mt < 2; mt++)
            #pragma unroll
            for (int nt = 0; nt < 8; nt++)
                #pragma unroll
                for (int r = 0; r < 4; r++) s_acc[mt][nt][r] = 0.f;
        #pragma unroll
        for (int ks = 0; ks < 4; ks++) {
            const int kk = ks * 16;
            uint32_t af[2][4];
            #pragma unroll
            for (int mt = 0; mt < 2; mt++)
                ldm4t(af[mt], s2u(&Qs[kk + (lane>>4)*8 + (lane&7)][wm*32 + mt*16 + ((lane>>3)&1)*8]));
            uint32_t kf[4][4];
            #pragma unroll
            for (int j4 = 0; j4 < 4; j4++)
                ldm4t(kf[j4], s2u(&Ks[st][kk + ((lane>>3)&1)*8 + (lane&7)][wn*64 + j4*16 + (lane>>4)*8]));
            #pragma unroll
            for (int nt = 0; nt < 8; nt++) {
                uint32_t b0 = kf[nt>>1][(nt&1)*2], b1 = kf[nt>>1][(nt&1)*2 + 1];
                mma16(s_acc[0][nt], af[0], b0, b1);
                mma16(s_acc[1][nt], af[1], b0, b1);
            }
        }

        // exp, row sums, P -> smem (bf16)
        #pragma unroll
        for (int mt = 0; mt < 2; mt++) {
            const int rm = wm * 32 + mt * 16 + (lane >> 2);
            float slo = 0.f, shi = 0.f;
            #pragma unroll
            for (int nt = 0; nt < 8; nt++) {
                const int sc2 = wn * 64 + nt * 8 + 2 * (lane & 3);
                float e0 = __expf(s_acc[mt][nt][0]);
                float e1 = __expf(s_acc[mt][nt][1]);
                float e2 = __expf(s_acc[mt][nt][2]);
                float e3 = __expf(s_acc[mt][nt][3]);
                slo += e0 + e1; shi += e2 + e3;
                *(uint32_t*)&Ps[rm][sc2]     = bfp(e0, e1);
                *(uint32_t*)&Ps[rm + 8][sc2] = bfp(e2, e3);
            }
            slo += __shfl_xor_sync(~0u, slo, 1); slo += __shfl_xor_sync(~0u, slo, 2);
            shi += __shfl_xor_sync(~0u, shi, 1); shi += __shfl_xor_sync(~0u, shi, 2);
            if ((lane & 3) == 0) { atomicAdd(&rs[rm], slo); atomicAdd(&rs[rm + 8], shi); }
        }
        CPWAIT(0);          // V(ck) landed (K(ck+1) also done; it had the whole S+exp phase)
        __syncthreads();

        // O += P V^T (m=t, n=d=64, k=s=128)
        #pragma unroll
        for (int ks = 0; ks < 8; ks++) {
            const int kk = ks * 16;
            uint32_t pa[2][4];
            #pragma unroll
            for (int mt = 0; mt < 2; mt++)
                ldm4(pa[mt], s2u(&Ps[wm*32 + mt*16 + ((lane>>3)&1)*8 + (lane&7)][kk + (lane>>4)*8]));
            uint32_t vb[2][4];
            #pragma unroll
            for (int j = 0; j < 2; j++)
                ldm4(vb[j], s2u(&Vs[wn*32 + j*16 + (lane>>4)*8 + (lane&7)][kk + ((lane>>3)&1)*8]));
            #pragma unroll
            for (int nt = 0; nt < 4; nt++) {
                uint32_t b0 = vb[nt>>1][(nt&1)*2], b1 = vb[nt>>1][(nt&1)*2 + 1];
                mma16(o_acc[0][nt], pa[0], b0, b1);
                mma16(o_acc[1][nt], pa[1], b0, b1);
            }
        }
        __syncthreads();    // Vs/Ps free for next chunk
    }

    // normalize + transpose via smem (reuse Ps as float [64][136]) + bf16 store
    float* Osm = (float*)Ps;
    #pragma unroll
    for (int mt = 0; mt < 2; mt++) {
        const int rm = wm * 32 + mt * 16 + (lane >> 2);
        const float ilo = 1.f / rs[rm], ihi = 1.f / rs[rm + 8];
        #pragma unroll
        for (int nt = 0; nt < 4; nt++) {
            const int d = wn * 32 + nt * 8 + 2 * (lane & 3);
            Osm[(size_t)d * 136 + rm]           = o_acc[mt][nt][0] * ilo;
            Osm[(size_t)(d + 1) * 136 + rm]     = o_acc[mt][nt][1] * ilo;
            Osm[(size_t)d * 136 + rm + 8]       = o_acc[mt][nt][2] * ihi;
            Osm[(size_t)(d + 1) * 136 + rm + 8] = o_acc[mt][nt][3] * ihi;
        }
    }
    __syncthreads();
    __nv_bfloat16* Og = att + ((size_t)b * 512 + h * 64) * 1024 + q0;
    #pragma unroll
    for (int it = 0; it < 8; it++) {
        int idx = tid + it * 256, d = idx >> 5, t4 = (idx & 31) * 4;
        const float* src = &Osm[(size_t)d * 136 + t4];
        *(uint2*)(Og + (size_t)d * 1024 + t4) = make_uint2(bfp(src[0], src[1]), bfp(src[2], src[3]));
    }
    #undef FILLK
    #undef FILLV
}

// ---------------- launch ----------------
extern "C" void kernel_launch(void* const* d_in, const int* in_sizes, int n_in,
                              void* d_out, int out_size)
{
    const float* x     = (const float*)d_in[0];
    const float* gamma = (const float*)d_in[1];
    const float* beta  = (const float*)d_in[2];
    const float* Wq    = (const float*)d_in[3];
    const float* bq    = (const float*)d_in[4];
    const float* Wkv   = (const float*)d_in[5];
    const float* bkv   = (const float*)d_in[6];
    const float* Wo    = (const float*)d_in[7];
    const float* bo    = (const float*)d_in[8];

    __nv_bfloat16* hn;  cudaGetSymbolAddress((void**)&hn,  g_hn);
    __nv_bfloat16* qkv; cudaGetSymbolAddress((void**)&qkv, g_qkv);
    __nv_bfloat16* att; cudaGetSymbolAddress((void**)&att, g_att);
    __nv_bfloat16* w;   cudaGetSymbolAddress((void**)&w,   g_w);

    prep_kernel<<<1024, 256>>>(Wq, Wkv, Wo, w);
    gn_kernel<<<256, 256>>>(x, gamma, beta, hn);
    {
        dim3 grid(8, 12, BATCH);
        gemm_mma<0><<<grid, 256>>>(w, bq, bkv, hn, nullptr, qkv);
    }
    {
        const int smem = 104960;
        cudaFuncSetAttribute(attn_mma, cudaFuncAttributeMaxDynamicSharedMemorySize, smem);
        dim3 grid(8, 8, BATCH);
        attn_mma<<<grid, 256, smem>>>(qkv, att);
    }
    {
        dim3 grid(8, 4, BATCH);
        gemm_mma<1><<<grid, 256>>>(w, bo, nullptr, att, x, d_out);
    }
}

// round 8
// speedup vs baseline: 7.9353x; 1.0749x over previous
#include <cuda_runtime.h>
#include <cuda_bf16.h>
#include <cstdint>

#define BATCH 8
#define LSEQ  1024
#define QK_SCALE 0.125f

// ---------------- scratch (no allocs allowed) ----------------
__device__ __nv_bfloat16 g_hn [(size_t)BATCH*512*LSEQ];    // [b][c][L]
__device__ __nv_bfloat16 g_qkv[(size_t)BATCH*1536*LSEQ];   // rows 0-511 q*s, 512-1023 k*s, 1024-1535 v
__device__ __nv_bfloat16 g_att[(size_t)BATCH*512*LSEQ];    // [b][inner][L]
__device__ __nv_bfloat16 g_w  [(size_t)2048*512];          // bf16 weights: Wq | Wkv | Wo

// ---------------- helpers ----------------
__device__ __forceinline__ uint32_t s2u(const void* p){
    uint32_t a;
    asm("{ .reg .u64 t; cvta.to.shared.u64 t, %1; cvt.u32.u64 %0, t; }" : "=r"(a) : "l"(p));
    return a;
}
__device__ __forceinline__ void ldm4(uint32_t* r, uint32_t a){
    asm volatile("ldmatrix.sync.aligned.m8n8.x4.shared.b16 {%0,%1,%2,%3}, [%4];"
        : "=r"(r[0]),"=r"(r[1]),"=r"(r[2]),"=r"(r[3]) : "r"(a));
}
__device__ __forceinline__ void ldm4t(uint32_t* r, uint32_t a){
    asm volatile("ldmatrix.sync.aligned.m8n8.x4.trans.shared.b16 {%0,%1,%2,%3}, [%4];"
        : "=r"(r[0]),"=r"(r[1]),"=r"(r[2]),"=r"(r[3]) : "r"(a));
}
__device__ __forceinline__ void mma16(float* d, const uint32_t* a, uint32_t b0, uint32_t b1){
    asm volatile("mma.sync.aligned.m16n8k16.row.col.f32.bf16.bf16.f32 "
        "{%0,%1,%2,%3}, {%4,%5,%6,%7}, {%8,%9}, {%0,%1,%2,%3};"
        : "+f"(d[0]),"+f"(d[1]),"+f"(d[2]),"+f"(d[3])
        : "r"(a[0]),"r"(a[1]),"r"(a[2]),"r"(a[3]), "r"(b0),"r"(b1));
}
__device__ __forceinline__ uint32_t bfp(float x, float y){
    __nv_bfloat162 t = __floats2bfloat162_rn(x, y);
    return *(uint32_t*)&t;
}
#define CPA(s, g)   asm volatile("cp.async.cg.shared.global [%0], [%1], 16;" :: "r"(s2u(s)), "l"(g))
#define CPCOMMIT()  asm volatile("cp.async.commit_group;" ::: "memory")
#define CPWAIT(n)   asm volatile("cp.async.wait_group %0;" :: "n"(n) : "memory")

// ---------------- 0) weight prep: fp32 -> bf16 ----------------
__global__ __launch_bounds__(256) void prep_kernel(const float* __restrict__ Wq,
    const float* __restrict__ Wkv, const float* __restrict__ Wo,
    __nv_bfloat16* __restrict__ w)
{
    const size_t off = ((size_t)blockIdx.x * 256 + threadIdx.x) * 4;
    const float* src;
    if (off < (size_t)512 * 512)            src = Wq + off;
    else if (off < (size_t)1536 * 512)      src = Wkv + (off - (size_t)512 * 512);
    else                                    src = Wo + (off - (size_t)1536 * 512);
    float4 v = *(const float4*)src;
    *(uint2*)(w + off) = make_uint2(bfp(v.x, v.y), bfp(v.z, v.w));
}

// ---------------- 1) GroupNorm -> bf16 hn[b][c][L] ----------------
__global__ __launch_bounds__(256) void gn_kernel(const float* __restrict__ x,
    const float* __restrict__ gamma, const float* __restrict__ beta,
    __nv_bfloat16* __restrict__ hn)
{
    const int b = blockIdx.x >> 5, g = blockIdx.x & 31;
    const float* xp = x + ((size_t)b * 512 + g * 16) * LSEQ;
    __nv_bfloat16* hp = hn + ((size_t)b * 512 + g * 16) * LSEQ;
    float s1 = 0.f, s2 = 0.f;
    for (int e = threadIdx.x * 4; e < 16 * LSEQ; e += 1024) {
        float4 v = *(const float4*)(xp + e);
        s1 += v.x + v.y + v.z + v.w;
        s2 += v.x * v.x + v.y * v.y + v.z * v.z + v.w * v.w;
    }
    __shared__ float r1[32], r2[32];
    #pragma unroll
    for (int o = 16; o > 0; o >>= 1) {
        s1 += __shfl_down_sync(~0u, s1, o); s2 += __shfl_down_sync(~0u, s2, o);
    }
    int wid = threadIdx.x >> 5, lid = threadIdx.x & 31;
    if (lid == 0) { r1[wid] = s1; r2[wid] = s2; }
    __syncthreads();
    if (wid == 0) {
        s1 = (lid < 8) ? r1[lid] : 0.f; s2 = (lid < 8) ? r2[lid] : 0.f;
        #pragma unroll
        for (int o = 4; o > 0; o >>= 1) {
            s1 += __shfl_down_sync(~0u, s1, o); s2 += __shfl_down_sync(~0u, s2, o);
        }
        if (lid == 0) { r1[0] = s1; r2[0] = s2; }
    }
    __syncthreads();
    const float mean = r1[0] * (1.f / 16384.f);
    const float rstd = rsqrtf(r2[0] * (1.f / 16384.f) - mean * mean + 1e-5f);
    for (int e = threadIdx.x * 4; e < 16 * LSEQ; e += 1024) {
        int c = g * 16 + (e >> 10);
        float ga = gamma[c] * rstd, be = beta[c] - mean * ga;
        float4 v = *(const float4*)(xp + e);
        *(uint2*)(hp + e) = make_uint2(bfp(v.x * ga + be, v.y * ga + be),
                                       bfp(v.z * ga + be, v.w * ga + be));
    }
}

// ---------------- 2/4) bf16 GEMM, cp.async 2-stage pipeline ----------------
template<int MODE>
__global__ __launch_bounds__(256, 2) void gemm_mma(
    const __nv_bfloat16* __restrict__ Wall,
    const float* __restrict__ b0v, const float* __restrict__ b1v,
    const __nv_bfloat16* __restrict__ Bg, const float* __restrict__ xres,
    void* __restrict__ Cout)
{
    __shared__ __nv_bfloat16 As[2][128][40];
    __shared__ __nv_bfloat16 Bs[2][32][136];

    const int tid = threadIdx.x, lane = tid & 31, wid = tid >> 5;
    const int wm = wid & 3, wn = wid >> 2;
    const int n0 = blockIdx.x * 128, m0 = blockIdx.y * 128, b = blockIdx.z;

    const __nv_bfloat16* A;
    const float* bias;
    if (MODE == 0) {
        A = Wall + (size_t)m0 * 512;
        bias = (m0 < 512) ? (b0v + m0) : (b1v + (m0 - 512));
    } else {
        A = Wall + (size_t)(1536 + m0) * 512;
        bias = b0v + m0;
    }
    const __nv_bfloat16* Bb = Bg + (size_t)b * 512 * 1024 + n0;

    float acc[2][8][4];
    #pragma unroll
    for (int mt = 0; mt < 2; mt++)
        #pragma unroll
        for (int nt = 0; nt < 8; nt++)
            #pragma unroll
            for (int r = 0; r < 4; r++) acc[mt][nt][r] = 0.f;

    const int ae_r = tid >> 1, ae_c = (tid & 1) * 16;
    const int be_k = tid >> 3, be_c = (tid & 7) * 16;

    #define FILL(st, kc) do { \
        CPA(&As[st][ae_r][ae_c],     A + (size_t)ae_r * 512 + (kc) + ae_c); \
        CPA(&As[st][ae_r][ae_c + 8], A + (size_t)ae_r * 512 + (kc) + ae_c + 8); \
        CPA(&Bs[st][be_k][be_c],     Bb + (size_t)((kc) + be_k) * 1024 + be_c); \
        CPA(&Bs[st][be_k][be_c + 8], Bb + (size_t)((kc) + be_k) * 1024 + be_c + 8); \
        CPCOMMIT(); } while (0)

    FILL(0, 0);
    #pragma unroll 1
    for (int i = 0; i < 16; i++) {
        const int st = i & 1;
        if (i + 1 < 16) { FILL(st ^ 1, (i + 1) * 32); CPWAIT(1); }
        else            { CPWAIT(0); }
        __syncthreads();
        #pragma unroll
        for (int ks = 0; ks < 2; ks++) {
            const int kk = ks * 16;
            uint32_t af[2][4];
            #pragma unroll
            for (int mt = 0; mt < 2; mt++)
                ldm4(af[mt], s2u(&As[st][wm*32 + mt*16 + ((lane>>3)&1)*8 + (lane&7)][kk + (lane>>4)*8]));
            uint32_t bf_[4][4];
            #pragma unroll
            for (int j4 = 0; j4 < 4; j4++)
                ldm4t(bf_[j4], s2u(&Bs[st][kk + ((lane>>3)&1)*8 + (lane&7)][wn*64 + j4*16 + (lane>>4)*8]));
            #pragma unroll
            for (int nt = 0; nt < 8; nt++) {
                uint32_t b0 = bf_[nt>>1][(nt&1)*2], b1 = bf_[nt>>1][(nt&1)*2 + 1];
                mma16(acc[0][nt], af[0], b0, b1);
                mma16(acc[1][nt], af[1], b0, b1);
            }
        }
        __syncthreads();
    }

    const float sc = (MODE == 0 && m0 < 1024) ? QK_SCALE : 1.0f;
    #pragma unroll
    for (int mt = 0; mt < 2; mt++) {
        const int loc = wm * 32 + mt * 16 + (lane >> 2);
        const int m = m0 + loc;
        const float bi0 = bias[loc], bi1 = bias[loc + 8];
        #pragma unroll
        for (int nt = 0; nt < 8; nt++) {
            const int nc = wn * 64 + nt * 8 + 2 * (lane & 3);
            float v00 = (acc[mt][nt][0] + bi0) * sc, v01 = (acc[mt][nt][1] + bi0) * sc;
            float v10 = (acc[mt][nt][2] + bi1) * sc, v11 = (acc[mt][nt][3] + bi1) * sc;
            if (MODE == 0) {
                __nv_bfloat16* row0 = (__nv_bfloat16*)Cout + ((size_t)b * 1536 + m) * 1024 + n0 + nc;
                *(uint32_t*)row0              = bfp(v00, v01);
                *(uint32_t*)(row0 + 8 * 1024) = bfp(v10, v11);
            } else {
                float* row0 = (float*)Cout + ((size_t)b * 512 + m) * 1024 + n0 + nc;
                const float* xr0 = xres + ((size_t)b * 512 + m) * 1024 + n0 + nc;
                float2 x0 = *(const float2*)xr0, x1 = *(const float2*)(xr0 + 8 * 1024);
                *(float2*)row0              = make_float2(v00 + x0.x, v01 + x0.y);
                *(float2*)(row0 + 8 * 1024) = make_float2(v10 + x1.x, v11 + x1.y);
            }
        }
    }
    #undef FILL
}

// ---------------- 3) FA2-style attention: register-resident P, K/V double buffered ----------------
// warp w owns q-rows [w*16, w*16+16); n spans all 128 s-cols -> P stays in registers.
// smem: Qs 17408 | Ks 2x17408 | Vs 2x17408 = 87040 -> 2 CTAs/SM
__global__ __launch_bounds__(256, 2) void attn_mma(const __nv_bfloat16* __restrict__ qkv,
                                                   __nv_bfloat16* __restrict__ att)
{
    extern __shared__ unsigned char dsm[];
    __nv_bfloat16 (*Qs)[136]     = (__nv_bfloat16(*)[136])(dsm);              // [64][136]
    __nv_bfloat16 (*Ks)[64][136] = (__nv_bfloat16(*)[64][136])(dsm + 17408);  // [2][64][136]
    __nv_bfloat16 (*Vs)[64][136] = (__nv_bfloat16(*)[64][136])(dsm + 52224);  // [2][64][136]

    const int tid = threadIdx.x, lane = tid & 31, wid = tid >> 5;
    const int b = blockIdx.z, h = blockIdx.y, q0 = blockIdx.x * 128;

    const __nv_bfloat16* Qg = qkv + ((size_t)b * 1536 + h * 64) * 1024 + q0;
    const __nv_bfloat16* Kg = qkv + ((size_t)b * 1536 + 512 + h * 64) * 1024;
    const __nv_bfloat16* Vg = qkv + ((size_t)b * 1536 + 1024 + h * 64) * 1024;

    const int fd = tid >> 2, fc = (tid & 3) * 32;
    #define FILLKV(st, s0) do { \
        _Pragma("unroll") \
        for (int j = 0; j < 4; j++) { \
            CPA(&Ks[st][fd][fc + j * 8], Kg + (size_t)fd * 1024 + (s0) + fc + j * 8); \
            CPA(&Vs[st][fd][fc + j * 8], Vg + (size_t)fd * 1024 + (s0) + fc + j * 8); } \
        CPCOMMIT(); } while (0)

    FILLKV(0, 0);
    #pragma unroll
    for (int it = 0; it < 4; it++) {
        int idx = tid + it * 256, d = idx >> 4, c8 = (idx & 15) * 8;
        *(uint4*)&Qs[d][c8] = *(const uint4*)(Qg + (size_t)d * 1024 + c8);
    }
    __syncthreads();

    // hoist Q fragments (A-frags, m16 per warp, k=64 -> 4 k16 steps)
    uint32_t qf[4][4];
    #pragma unroll
    for (int ks = 0; ks < 4; ks++)
        ldm4t(qf[ks], s2u(&Qs[ks*16 + (lane>>4)*8 + (lane&7)][wid*16 + ((lane>>3)&1)*8]));

    float o_acc[8][4];
    #pragma unroll
    for (int nt = 0; nt < 8; nt++)
        #pragma unroll
        for (int r = 0; r < 4; r++) o_acc[nt][r] = 0.f;
    float sum_lo = 0.f, sum_hi = 0.f;

    #pragma unroll 1
    for (int ck = 0; ck < 8; ck++) {
        const int st = ck & 1;
        __syncthreads();                       // all reads of buffer st^1 (chunk ck-1) done
        if (ck + 1 < 8) { FILLKV(st ^ 1, (ck + 1) * 128); CPWAIT(1); }
        else            { CPWAIT(0); }
        __syncthreads();                       // K/V(ck) visible to all

        #pragma unroll
        for (int hf = 0; hf < 2; hf++) {       // two n-halves (s-cols 0-63, 64-127)
            const int nb = hf * 64;
            // S half: m16 x n64, k=64
            float s_acc[8][4];
            #pragma unroll
            for (int nt = 0; nt < 8; nt++)
                #pragma unroll
                for (int r = 0; r < 4; r++) s_acc[nt][r] = 0.f;
            #pragma unroll
            for (int ks = 0; ks < 4; ks++) {
                const int kk = ks * 16;
                uint32_t kf[4][4];
                #pragma unroll
                for (int j4 = 0; j4 < 4; j4++)
                    ldm4t(kf[j4], s2u(&Ks[st][kk + ((lane>>3)&1)*8 + (lane&7)][nb + j4*16 + (lane>>4)*8]));
                #pragma unroll
                for (int nt = 0; nt < 8; nt++)
                    mma16(s_acc[nt], qf[ks], kf[nt>>1][(nt&1)*2], kf[nt>>1][(nt&1)*2 + 1]);
            }
            // exp -> pack directly into PV A-fragments (accum layout == A-frag layout)
            uint32_t pf[4][4];
            #pragma unroll
            for (int j = 0; j < 4; j++) {
                float e0 = __expf(s_acc[2*j][0]),   e1 = __expf(s_acc[2*j][1]);
                float e2 = __expf(s_acc[2*j][2]),   e3 = __expf(s_acc[2*j][3]);
                float f0 = __expf(s_acc[2*j+1][0]), f1 = __expf(s_acc[2*j+1][1]);
                float f2 = __expf(s_acc[2*j+1][2]), f3 = __expf(s_acc[2*j+1][3]);
                sum_lo += (e0 + e1) + (f0 + f1);
                sum_hi += (e2 + e3) + (f2 + f3);
                pf[j][0] = bfp(e0, e1); pf[j][1] = bfp(e2, e3);
                pf[j][2] = bfp(f0, f1); pf[j][3] = bfp(f2, f3);
            }
            // O += P V^T  (m=t16, n=d64, k=s64 of this half)
            #pragma unroll
            for (int j = 0; j < 4; j++) {
                const int kk = nb + j * 16;
                uint32_t vb[4][4];
                #pragma unroll
                for (int j4 = 0; j4 < 4; j4++)
                    ldm4(vb[j4], s2u(&Vs[st][j4*16 + (lane>>4)*8 + (lane&7)][kk + ((lane>>3)&1)*8]));
                #pragma unroll
                for (int nt = 0; nt < 8; nt++)
                    mma16(o_acc[nt], pf[j], vb[nt>>1][(nt&1)*2], vb[nt>>1][(nt&1)*2 + 1]);
            }
        }
    }

    // row-sum reduce within quad (cols split across lane&3)
    sum_lo += __shfl_xor_sync(~0u, sum_lo, 1); sum_lo += __shfl_xor_sync(~0u, sum_lo, 2);
    sum_hi += __shfl_xor_sync(~0u, sum_hi, 1); sum_hi += __shfl_xor_sync(~0u, sum_hi, 2);
    const float ilo = 1.f / sum_lo, ihi = 1.f / sum_hi;

    // normalize + transpose via smem (reuse Ks region as float [64][136]) + bf16 store
    __syncthreads();
    float* Osm = (float*)(dsm + 17408);
    const int rlo = wid * 16 + (lane >> 2);
    #pragma unroll
    for (int nt = 0; nt < 8; nt++) {
        const int d = nt * 8 + 2 * (lane & 3);
        Osm[(size_t)d * 136 + rlo]           = o_acc[nt][0] * ilo;
        Osm[(size_t)(d + 1) * 136 + rlo]     = o_acc[nt][1] * ilo;
        Osm[(size_t)d * 136 + rlo + 8]       = o_acc[nt][2] * ihi;
        Osm[(size_t)(d + 1) * 136 + rlo + 8] = o_acc[nt][3] * ihi;
    }
    __syncthreads();
    __nv_bfloat16* Og = att + ((size_t)b * 512 + h * 64) * 1024 + q0;
    #pragma unroll
    for (int it = 0; it < 8; it++) {
        int idx = tid + it * 256, d = idx >> 5, t4 = (idx & 31) * 4;
        const float* src = &Osm[(size_t)d * 136 + t4];
        *(uint2*)(Og + (size_t)d * 1024 + t4) = make_uint2(bfp(src[0], src[1]), bfp(src[2], src[3]));
    }
    #undef FILLKV
}

// ---------------- launch ----------------
extern "C" void kernel_launch(void* const* d_in, const int* in_sizes, int n_in,
                              void* d_out, int out_size)
{
    const float* x     = (const float*)d_in[0];
    const float* gamma = (const float*)d_in[1];
    const float* beta  = (const float*)d_in[2];
    const float* Wq    = (const float*)d_in[3];
    const float* bq    = (const float*)d_in[4];
    const float* Wkv   = (const float*)d_in[5];
    const float* bkv   = (const float*)d_in[6];
    const float* Wo    = (const float*)d_in[7];
    const float* bo    = (const float*)d_in[8];

    __nv_bfloat16* hn;  cudaGetSymbolAddress((void**)&hn,  g_hn);
    __nv_bfloat16* qkv; cudaGetSymbolAddress((void**)&qkv, g_qkv);
    __nv_bfloat16* att; cudaGetSymbolAddress((void**)&att, g_att);
    __nv_bfloat16* w;   cudaGetSymbolAddress((void**)&w,   g_w);

    prep_kernel<<<1024, 256>>>(Wq, Wkv, Wo, w);
    gn_kernel<<<256, 256>>>(x, gamma, beta, hn);
    {
        dim3 grid(8, 12, BATCH);
        gemm_mma<0><<<grid, 256>>>(w, bq, bkv, hn, nullptr, qkv);
    }
    {
        const int smem = 87040;
        cudaFuncSetAttribute(attn_mma, cudaFuncAttributeMaxDynamicSharedMemorySize, smem);
        dim3 grid(8, 8, BATCH);
        attn_mma<<<grid, 256, smem>>>(qkv, att);
    }
    {
        dim3 grid(8, 4, BATCH);
        gemm_mma<1><<<grid, 256>>>(w, bo, nullptr, att, x, d_out);
    }
}

// round 9
// speedup vs baseline: 8.6631x; 1.0917x over previous
#include <cuda_runtime.h>
#include <cuda_bf16.h>
#include <cstdint>

#define BATCH 8
#define LSEQ  1024
#define QK_SCALE 0.125f

// ---------------- scratch (no allocs allowed) ----------------
__device__ __nv_bfloat16 g_hn [(size_t)BATCH*512*LSEQ];    // [b][c][L]
__device__ __nv_bfloat16 g_qkv[(size_t)BATCH*1536*LSEQ];   // rows 0-511 q*s, 512-1023 k*s, 1024-1535 v
__device__ __nv_bfloat16 g_att[(size_t)BATCH*512*LSEQ];    // [b][inner][L]
__device__ __nv_bfloat16 g_w  [(size_t)2048*512];          // bf16 weights: Wq | Wkv | Wo

// ---------------- helpers ----------------
__device__ __forceinline__ uint32_t s2u(const void* p){
    uint32_t a;
    asm("{ .reg .u64 t; cvta.to.shared.u64 t, %1; cvt.u32.u64 %0, t; }" : "=r"(a) : "l"(p));
    return a;
}
__device__ __forceinline__ void ldm4(uint32_t* r, uint32_t a){
    asm volatile("ldmatrix.sync.aligned.m8n8.x4.shared.b16 {%0,%1,%2,%3}, [%4];"
        : "=r"(r[0]),"=r"(r[1]),"=r"(r[2]),"=r"(r[3]) : "r"(a));
}
__device__ __forceinline__ void ldm4t(uint32_t* r, uint32_t a){
    asm volatile("ldmatrix.sync.aligned.m8n8.x4.trans.shared.b16 {%0,%1,%2,%3}, [%4];"
        : "=r"(r[0]),"=r"(r[1]),"=r"(r[2]),"=r"(r[3]) : "r"(a));
}
__device__ __forceinline__ void mma16(float* d, const uint32_t* a, uint32_t b0, uint32_t b1){
    asm volatile("mma.sync.aligned.m16n8k16.row.col.f32.bf16.bf16.f32 "
        "{%0,%1,%2,%3}, {%4,%5,%6,%7}, {%8,%9}, {%0,%1,%2,%3};"
        : "+f"(d[0]),"+f"(d[1]),"+f"(d[2]),"+f"(d[3])
        : "r"(a[0]),"r"(a[1]),"r"(a[2]),"r"(a[3]), "r"(b0),"r"(b1));
}
__device__ __forceinline__ uint32_t bfp(float x, float y){
    __nv_bfloat162 t = __floats2bfloat162_rn(x, y);
    return *(uint32_t*)&t;
}
#define CPAu(s, g)  asm volatile("cp.async.cg.shared.global [%0], [%1], 16;" :: "r"(s), "l"(g))
#define CPCOMMIT()  asm volatile("cp.async.commit_group;" ::: "memory")
#define CPWAIT(n)   asm volatile("cp.async.wait_group %0;" :: "n"(n) : "memory")

// ---------------- 0) weight prep: fp32 -> bf16 ----------------
__global__ __launch_bounds__(256) void prep_kernel(const float* __restrict__ Wq,
    const float* __restrict__ Wkv, const float* __restrict__ Wo,
    __nv_bfloat16* __restrict__ w)
{
    const size_t off = ((size_t)blockIdx.x * 256 + threadIdx.x) * 4;
    const float* src;
    if (off < (size_t)512 * 512)            src = Wq + off;
    else if (off < (size_t)1536 * 512)      src = Wkv + (off - (size_t)512 * 512);
    else                                    src = Wo + (off - (size_t)1536 * 512);
    float4 v = *(const float4*)src;
    *(uint2*)(w + off) = make_uint2(bfp(v.x, v.y), bfp(v.z, v.w));
}

// ---------------- 1) GroupNorm -> bf16 hn[b][c][L] ----------------
__global__ __launch_bounds__(256) void gn_kernel(const float* __restrict__ x,
    const float* __restrict__ gamma, const float* __restrict__ beta,
    __nv_bfloat16* __restrict__ hn)
{
    const int b = blockIdx.x >> 5, g = blockIdx.x & 31;
    const float* xp = x + ((size_t)b * 512 + g * 16) * LSEQ;
    __nv_bfloat16* hp = hn + ((size_t)b * 512 + g * 16) * LSEQ;
    float s1 = 0.f, s2 = 0.f;
    for (int e = threadIdx.x * 4; e < 16 * LSEQ; e += 1024) {
        float4 v = *(const float4*)(xp + e);
        s1 += v.x + v.y + v.z + v.w;
        s2 += v.x * v.x + v.y * v.y + v.z * v.z + v.w * v.w;
    }
    __shared__ float r1[32], r2[32];
    #pragma unroll
    for (int o = 16; o > 0; o >>= 1) {
        s1 += __shfl_down_sync(~0u, s1, o); s2 += __shfl_down_sync(~0u, s2, o);
    }
    int wid = threadIdx.x >> 5, lid = threadIdx.x & 31;
    if (lid == 0) { r1[wid] = s1; r2[wid] = s2; }
    __syncthreads();
    if (wid == 0) {
        s1 = (lid < 8) ? r1[lid] : 0.f; s2 = (lid < 8) ? r2[lid] : 0.f;
        #pragma unroll
        for (int o = 4; o > 0; o >>= 1) {
            s1 += __shfl_down_sync(~0u, s1, o); s2 += __shfl_down_sync(~0u, s2, o);
        }
        if (lid == 0) { r1[0] = s1; r2[0] = s2; }
    }
    __syncthreads();
    const float mean = r1[0] * (1.f / 16384.f);
    const float rstd = rsqrtf(r2[0] * (1.f / 16384.f) - mean * mean + 1e-5f);
    for (int e = threadIdx.x * 4; e < 16 * LSEQ; e += 1024) {
        int c = g * 16 + (e >> 10);
        float ga = gamma[c] * rstd, be = beta[c] - mean * ga;
        float4 v = *(const float4*)(xp + e);
        *(uint2*)(hp + e) = make_uint2(bfp(v.x * ga + be, v.y * ga + be),
                                       bfp(v.z * ga + be, v.w * ga + be));
    }
}

// ---------------- 2/4) bf16 GEMM, 3-stage cp.async, 1 sync/chunk ----------------
// smem: A 3x10240 | B 3x8704 = 56832
#define G_BOFF 30720
template<int MODE>
__global__ __launch_bounds__(256, 2) void gemm_mma(
    const __nv_bfloat16* __restrict__ Wall,
    const float* __restrict__ b0v, const float* __restrict__ b1v,
    const __nv_bfloat16* __restrict__ Bg, const float* __restrict__ xres,
    void* __restrict__ Cout)
{
    extern __shared__ unsigned char gsm[];
    const uint32_t sb = s2u(gsm);
    const int tid = threadIdx.x, lane = tid & 31, wid = tid >> 5;
    const int wm = wid & 3, wn = wid >> 2;
    const int n0 = blockIdx.x * 128, m0 = blockIdx.y * 128, b = blockIdx.z;

    const __nv_bfloat16* A;
    const float* bias;
    if (MODE == 0) {
        A = Wall + (size_t)m0 * 512;
        bias = (m0 < 512) ? (b0v + m0) : (b1v + (m0 - 512));
    } else {
        A = Wall + (size_t)(1536 + m0) * 512;
        bias = b0v + m0;
    }
    const __nv_bfloat16* Bb = Bg + (size_t)b * 512 * 1024 + n0;

    float acc[2][8][4];
    #pragma unroll
    for (int mt = 0; mt < 2; mt++)
        #pragma unroll
        for (int nt = 0; nt < 8; nt++)
            #pragma unroll
            for (int r = 0; r < 4; r++) acc[mt][nt][r] = 0.f;

    // fill addresses (hoisted)
    const int ae_r = tid >> 1, ae_c = (tid & 1) * 16;
    const int be_k = tid >> 3, be_c = (tid & 7) * 16;
    const uint32_t afill = sb + ae_r * 80 + ae_c * 2;
    const uint32_t bfill = sb + G_BOFF + be_k * 272 + be_c * 2;
    const __nv_bfloat16* agp = A + (size_t)ae_r * 512 + ae_c;
    const __nv_bfloat16* bgp = Bb + (size_t)be_k * 1024 + be_c;

    #define FILL(st, kc) do { \
        CPAu(afill + (st) * 10240,      agp + (kc)); \
        CPAu(afill + (st) * 10240 + 16, agp + (kc) + 8); \
        CPAu(bfill + (st) * 8704,       bgp + (size_t)(kc) * 1024); \
        CPAu(bfill + (st) * 8704 + 16,  bgp + (size_t)(kc) * 1024 + 8); \
        CPCOMMIT(); } while (0)

    // frag addresses (hoisted)
    const uint32_t afrag = sb + (wm*32 + ((lane>>3)&1)*8 + (lane&7)) * 80 + ((lane>>4)*8) * 2;
    const uint32_t bfrag = sb + G_BOFF + (((lane>>3)&1)*8 + (lane&7)) * 272 + (wn*64 + (lane>>4)*8) * 2;

    FILL(0, 0); FILL(1, 32);
    #pragma unroll 1
    for (int i = 0; i < 16; i++) {
        const int st = i - (i / 3) * 3;          // i % 3
        if (i < 15) CPWAIT(1); else CPWAIT(0);
        __syncthreads();
        if (i + 2 < 16) {
            const int st2 = (i + 2) - ((i + 2) / 3) * 3;
            FILL(st2, (i + 2) * 32);
        }
        const uint32_t aoff = afrag + st * 10240, boff = bfrag + st * 8704;
        #pragma unroll
        for (int ks = 0; ks < 2; ks++) {
            const int kk = ks * 16;
            uint32_t af[2][4];
            #pragma unroll
            for (int mt = 0; mt < 2; mt++)
                ldm4(af[mt], aoff + mt * (16 * 80) + kk * 2);
            uint32_t bf_[4][4];
            #pragma unroll
            for (int j4 = 0; j4 < 4; j4++)
                ldm4t(bf_[j4], boff + kk * 272 + j4 * 32);
            #pragma unroll
            for (int nt = 0; nt < 8; nt++) {
                uint32_t b0 = bf_[nt>>1][(nt&1)*2], b1 = bf_[nt>>1][(nt&1)*2 + 1];
                mma16(acc[0][nt], af[0], b0, b1);
                mma16(acc[1][nt], af[1], b0, b1);
            }
        }
    }

    const float sc = (MODE == 0 && m0 < 1024) ? QK_SCALE : 1.0f;
    #pragma unroll
    for (int mt = 0; mt < 2; mt++) {
        const int loc = wm * 32 + mt * 16 + (lane >> 2);
        const int m = m0 + loc;
        const float bi0 = bias[loc], bi1 = bias[loc + 8];
        #pragma unroll
        for (int nt = 0; nt < 8; nt++) {
            const int nc = wn * 64 + nt * 8 + 2 * (lane & 3);
            float v00 = (acc[mt][nt][0] + bi0) * sc, v01 = (acc[mt][nt][1] + bi0) * sc;
            float v10 = (acc[mt][nt][2] + bi1) * sc, v11 = (acc[mt][nt][3] + bi1) * sc;
            if (MODE == 0) {
                __nv_bfloat16* row0 = (__nv_bfloat16*)Cout + ((size_t)b * 1536 + m) * 1024 + n0 + nc;
                *(uint32_t*)row0              = bfp(v00, v01);
                *(uint32_t*)(row0 + 8 * 1024) = bfp(v10, v11);
            } else {
                float* row0 = (float*)Cout + ((size_t)b * 512 + m) * 1024 + n0 + nc;
                const float* xr0 = xres + ((size_t)b * 512 + m) * 1024 + n0 + nc;
                float2 x0 = *(const float2*)xr0, x1 = *(const float2*)(xr0 + 8 * 1024);
                *(float2*)row0              = make_float2(v00 + x0.x, v01 + x0.y);
                *(float2*)(row0 + 8 * 1024) = make_float2(v10 + x1.x, v11 + x1.y);
            }
        }
    }
    #undef FILL
}

// ---------------- 3) FA2 attention: reg-resident P, 3-stage K/V, 1 sync/chunk ----------------
// smem: K bufs at 0/17408/34816, V bufs at 52224/69632/87040 = 104448; Q overlays K buf 0.
#define A_VOFF 52224
__global__ __launch_bounds__(256, 2) void attn_mma(const __nv_bfloat16* __restrict__ qkv,
                                                   __nv_bfloat16* __restrict__ att)
{
    extern __shared__ unsigned char dsm[];
    const uint32_t sb = s2u(dsm);
    const int tid = threadIdx.x, lane = tid & 31, wid = tid >> 5;
    const int b = blockIdx.z, h = blockIdx.y, q0 = blockIdx.x * 128;

    const __nv_bfloat16* Qg = qkv + ((size_t)b * 1536 + h * 64) * 1024 + q0;
    const __nv_bfloat16* Kg = qkv + ((size_t)b * 1536 + 512 + h * 64) * 1024;
    const __nv_bfloat16* Vg = qkv + ((size_t)b * 1536 + 1024 + h * 64) * 1024;

    // Q into K-buf-0 region, extract fragments, then recycle
    __nv_bfloat16 (*Qs)[136] = (__nv_bfloat16(*)[136])(dsm);
    #pragma unroll
    for (int it = 0; it < 4; it++) {
        int idx = tid + it * 256, d = idx >> 4, c8 = (idx & 15) * 8;
        *(uint4*)&Qs[d][c8] = *(const uint4*)(Qg + (size_t)d * 1024 + c8);
    }
    __syncthreads();
    uint32_t qf[4][4];
    #pragma unroll
    for (int ks = 0; ks < 4; ks++)
        ldm4t(qf[ks], sb + (ks*16 + (lane>>4)*8 + (lane&7)) * 272 + (wid*16 + ((lane>>3)&1)*8) * 2);
    __syncthreads();

    // fill addresses (hoisted)
    const int fd = tid >> 2, fc = (tid & 3) * 32;
    const uint32_t kfill = sb + fd * 272 + fc * 2;
    const uint32_t vfill = sb + A_VOFF + fd * 272 + fc * 2;
    const __nv_bfloat16* kgp = Kg + (size_t)fd * 1024 + fc;
    const __nv_bfloat16* vgp = Vg + (size_t)fd * 1024 + fc;
    #define FILLKV(stoff, s0) do { \
        _Pragma("unroll") \
        for (int j = 0; j < 4; j++) { \
            CPAu(kfill + (stoff) + j * 16, kgp + (s0) + j * 8); \
            CPAu(vfill + (stoff) + j * 16, vgp + (s0) + j * 8); } \
        CPCOMMIT(); } while (0)

    // frag addresses (hoisted)
    const uint32_t kfrag = sb + (((lane>>3)&1)*8 + (lane&7)) * 272 + ((lane>>4)*8) * 2;
    const uint32_t vfrag = sb + A_VOFF + ((lane>>4)*8 + (lane&7)) * 272 + (((lane>>3)&1)*8) * 2;

    float o_acc[8][4];
    #pragma unroll
    for (int nt = 0; nt < 8; nt++)
        #pragma unroll
        for (int r = 0; r < 4; r++) o_acc[nt][r] = 0.f;
    float sum_lo = 0.f, sum_hi = 0.f;

    FILLKV(0, 0); FILLKV(17408, 128);
    #pragma unroll 1
    for (int ck = 0; ck < 8; ck++) {
        const int st = ck - (ck / 3) * 3;       // ck % 3
        if (ck < 7) CPWAIT(1); else CPWAIT(0);
        __syncthreads();                         // K/V(ck) visible; all warps done chunk ck-1
        if (ck + 2 < 8) {
            const int st2 = (ck + 2) - ((ck + 2) / 3) * 3;
            FILLKV(st2 * 17408, (ck + 2) * 128);
        }
        const uint32_t koff = kfrag + st * 17408, voff = vfrag + st * 17408;

        #pragma unroll
        for (int hf = 0; hf < 2; hf++) {
            const int nb = hf * 64;
            float s_acc[8][4];
            #pragma unroll
            for (int nt = 0; nt < 8; nt++)
                #pragma unroll
                for (int r = 0; r < 4; r++) s_acc[nt][r] = 0.f;
            #pragma unroll
            for (int ks = 0; ks < 4; ks++) {
                uint32_t kf[4][4];
                #pragma unroll
                for (int j4 = 0; j4 < 4; j4++)
                    ldm4t(kf[j4], koff + ks * (16 * 272) + (nb + j4 * 16) * 2);
                #pragma unroll
                for (int nt = 0; nt < 8; nt++)
                    mma16(s_acc[nt], qf[ks], kf[nt>>1][(nt&1)*2], kf[nt>>1][(nt&1)*2 + 1]);
            }
            uint32_t pf[4][4];
            #pragma unroll
            for (int j = 0; j < 4; j++) {
                float e0 = __expf(s_acc[2*j][0]),   e1 = __expf(s_acc[2*j][1]);
                float e2 = __expf(s_acc[2*j][2]),   e3 = __expf(s_acc[2*j][3]);
                float f0 = __expf(s_acc[2*j+1][0]), f1 = __expf(s_acc[2*j+1][1]);
                float f2 = __expf(s_acc[2*j+1][2]), f3 = __expf(s_acc[2*j+1][3]);
                sum_lo += (e0 + e1) + (f0 + f1);
                sum_hi += (e2 + e3) + (f2 + f3);
                pf[j][0] = bfp(e0, e1); pf[j][1] = bfp(e2, e3);
                pf[j][2] = bfp(f0, f1); pf[j][3] = bfp(f2, f3);
            }
            #pragma unroll
            for (int j = 0; j < 4; j++) {
                const int kk = nb + j * 16;
                uint32_t vb[4][4];
                #pragma unroll
                for (int j4 = 0; j4 < 4; j4++)
                    ldm4(vb[j4], voff + j4 * (16 * 272) + kk * 2);
                #pragma unroll
                for (int nt = 0; nt < 8; nt++)
                    mma16(o_acc[nt], pf[j], vb[nt>>1][(nt&1)*2], vb[nt>>1][(nt&1)*2 + 1]);
            }
        }
    }

    sum_lo += __shfl_xor_sync(~0u, sum_lo, 1); sum_lo += __shfl_xor_sync(~0u, sum_lo, 2);
    sum_hi += __shfl_xor_sync(~0u, sum_hi, 1); sum_hi += __shfl_xor_sync(~0u, sum_hi, 2);
    const float ilo = 1.f / sum_lo, ihi = 1.f / sum_hi;

    __syncthreads();
    float* Osm = (float*)dsm;
    const int rlo = wid * 16 + (lane >> 2);
    #pragma unroll
    for (int nt = 0; nt < 8; nt++) {
        const int d = nt * 8 + 2 * (lane & 3);
        Osm[(size_t)d * 136 + rlo]           = o_acc[nt][0] * ilo;
        Osm[(size_t)(d + 1) * 136 + rlo]     = o_acc[nt][1] * ilo;
        Osm[(size_t)d * 136 + rlo + 8]       = o_acc[nt][2] * ihi;
        Osm[(size_t)(d + 1) * 136 + rlo + 8] = o_acc[nt][3] * ihi;
    }
    __syncthreads();
    __nv_bfloat16* Og = att + ((size_t)b * 512 + h * 64) * 1024 + q0;
    #pragma unroll
    for (int it = 0; it < 8; it++) {
        int idx = tid + it * 256, d = idx >> 5, t4 = (idx & 31) * 4;
        const float* src = &Osm[(size_t)d * 136 + t4];
        *(uint2*)(Og + (size_t)d * 1024 + t4) = make_uint2(bfp(src[0], src[1]), bfp(src[2], src[3]));
    }
    #undef FILLKV
}

// ---------------- launch ----------------
extern "C" void kernel_launch(void* const* d_in, const int* in_sizes, int n_in,
                              void* d_out, int out_size)
{
    const float* x     = (const float*)d_in[0];
    const float* gamma = (const float*)d_in[1];
    const float* beta  = (const float*)d_in[2];
    const float* Wq    = (const float*)d_in[3];
    const float* bq    = (const float*)d_in[4];
    const float* Wkv   = (const float*)d_in[5];
    const float* bkv   = (const float*)d_in[6];
    const float* Wo    = (const float*)d_in[7];
    const float* bo    = (const float*)d_in[8];

    __nv_bfloat16* hn;  cudaGetSymbolAddress((void**)&hn,  g_hn);
    __nv_bfloat16* qkv; cudaGetSymbolAddress((void**)&qkv, g_qkv);
    __nv_bfloat16* att; cudaGetSymbolAddress((void**)&att, g_att);
    __nv_bfloat16* w;   cudaGetSymbolAddress((void**)&w,   g_w);

    prep_kernel<<<1024, 256>>>(Wq, Wkv, Wo, w);
    gn_kernel<<<256, 256>>>(x, gamma, beta, hn);
    {
        cudaFuncSetAttribute(gemm_mma<0>, cudaFuncAttributeMaxDynamicSharedMemorySize, 56832);
        dim3 grid(8, 12, BATCH);
        gemm_mma<0><<<grid, 256, 56832>>>(w, bq, bkv, hn, nullptr, qkv);
    }
    {
        cudaFuncSetAttribute(attn_mma, cudaFuncAttributeMaxDynamicSharedMemorySize, 104448);
        dim3 grid(8, 8, BATCH);
        attn_mma<<<grid, 256, 104448>>>(qkv, att);
    }
    {
        cudaFuncSetAttribute(gemm_mma<1>, cudaFuncAttributeMaxDynamicSharedMemorySize, 56832);
        dim3 grid(8, 4, BATCH);
        gemm_mma<1><<<grid, 256, 56832>>>(w, bo, nullptr, att, x, d_out);
    }
}

// round 10
// speedup vs baseline: 8.7484x; 1.0098x over previous
#include <cuda_runtime.h>
#include <cuda_bf16.h>
#include <cstdint>

#define BATCH 8
#define LSEQ  1024
#define QK_SCALE 0.125f

// ---------------- scratch (no allocs allowed) ----------------
__device__ __nv_bfloat16 g_hn [(size_t)BATCH*512*LSEQ];    // [b][c][L]
__device__ __nv_bfloat16 g_qkv[(size_t)BATCH*1536*LSEQ];   // rows 0-511 q*s, 512-1023 k*s, 1024-1535 v
__device__ __nv_bfloat16 g_att[(size_t)BATCH*512*LSEQ];    // [b][inner][L]
__device__ __nv_bfloat16 g_w  [(size_t)2048*512];          // bf16 weights: Wq | Wkv | Wo

// ---------------- helpers ----------------
__device__ __forceinline__ uint32_t s2u(const void* p){
    uint32_t a;
    asm("{ .reg .u64 t; cvta.to.shared.u64 t, %1; cvt.u32.u64 %0, t; }" : "=r"(a) : "l"(p));
    return a;
}
__device__ __forceinline__ void ldm4(uint32_t* r, uint32_t a){
    asm volatile("ldmatrix.sync.aligned.m8n8.x4.shared.b16 {%0,%1,%2,%3}, [%4];"
        : "=r"(r[0]),"=r"(r[1]),"=r"(r[2]),"=r"(r[3]) : "r"(a));
}
__device__ __forceinline__ void ldm4t(uint32_t* r, uint32_t a){
    asm volatile("ldmatrix.sync.aligned.m8n8.x4.trans.shared.b16 {%0,%1,%2,%3}, [%4];"
        : "=r"(r[0]),"=r"(r[1]),"=r"(r[2]),"=r"(r[3]) : "r"(a));
}
__device__ __forceinline__ void mma16(float* d, const uint32_t* a, uint32_t b0, uint32_t b1){
    asm volatile("mma.sync.aligned.m16n8k16.row.col.f32.bf16.bf16.f32 "
        "{%0,%1,%2,%3}, {%4,%5,%6,%7}, {%8,%9}, {%0,%1,%2,%3};"
        : "+f"(d[0]),"+f"(d[1]),"+f"(d[2]),"+f"(d[3])
        : "r"(a[0]),"r"(a[1]),"r"(a[2]),"r"(a[3]), "r"(b0),"r"(b1));
}
__device__ __forceinline__ uint32_t bfp(float x, float y){
    __nv_bfloat162 t = __floats2bfloat162_rn(x, y);
    return *(uint32_t*)&t;
}
#define CPAu(s, g)  asm volatile("cp.async.cg.shared.global [%0], [%1], 16;" :: "r"(s), "l"(g))
#define CPCOMMIT()  asm volatile("cp.async.commit_group;" ::: "memory")
#define CPWAIT(n)   asm volatile("cp.async.wait_group %0;" :: "n"(n) : "memory")

// ---------------- 0) weight prep: fp32 -> bf16 ----------------
__global__ __launch_bounds__(256) void prep_kernel(const float* __restrict__ Wq,
    const float* __restrict__ Wkv, const float* __restrict__ Wo,
    __nv_bfloat16* __restrict__ w)
{
    const size_t off = ((size_t)blockIdx.x * 256 + threadIdx.x) * 4;
    const float* src;
    if (off < (size_t)512 * 512)            src = Wq + off;
    else if (off < (size_t)1536 * 512)      src = Wkv + (off - (size_t)512 * 512);
    else                                    src = Wo + (off - (size_t)1536 * 512);
    float4 v = *(const float4*)src;
    *(uint2*)(w + off) = make_uint2(bfp(v.x, v.y), bfp(v.z, v.w));
}

// ---------------- 1) GroupNorm (one-pass, smem-cached) -> bf16 hn[b][c][L] ----------------
__global__ __launch_bounds__(256) void gn_kernel(const float* __restrict__ x,
    const float* __restrict__ gamma, const float* __restrict__ beta,
    __nv_bfloat16* __restrict__ hn)
{
    extern __shared__ float xs[];            // 16*1024 floats = 64KB
    const int b = blockIdx.x >> 5, g = blockIdx.x & 31;
    const float* xp = x + ((size_t)b * 512 + g * 16) * LSEQ;
    __nv_bfloat16* hp = hn + ((size_t)b * 512 + g * 16) * LSEQ;
    float s1 = 0.f, s2 = 0.f;
    for (int e = threadIdx.x * 4; e < 16 * LSEQ; e += 1024) {
        float4 v = *(const float4*)(xp + e);
        *(float4*)(xs + e) = v;
        s1 += v.x + v.y + v.z + v.w;
        s2 += v.x * v.x + v.y * v.y + v.z * v.z + v.w * v.w;
    }
    __shared__ float r1[32], r2[32];
    #pragma unroll
    for (int o = 16; o > 0; o >>= 1) {
        s1 += __shfl_down_sync(~0u, s1, o); s2 += __shfl_down_sync(~0u, s2, o);
    }
    int wid = threadIdx.x >> 5, lid = threadIdx.x & 31;
    if (lid == 0) { r1[wid] = s1; r2[wid] = s2; }
    __syncthreads();
    if (wid == 0) {
        s1 = (lid < 8) ? r1[lid] : 0.f; s2 = (lid < 8) ? r2[lid] : 0.f;
        #pragma unroll
        for (int o = 4; o > 0; o >>= 1) {
            s1 += __shfl_down_sync(~0u, s1, o); s2 += __shfl_down_sync(~0u, s2, o);
        }
        if (lid == 0) { r1[0] = s1; r2[0] = s2; }
    }
    __syncthreads();
    const float mean = r1[0] * (1.f / 16384.f);
    const float rstd = rsqrtf(r2[0] * (1.f / 16384.f) - mean * mean + 1e-5f);
    for (int e = threadIdx.x * 4; e < 16 * LSEQ; e += 1024) {
        int c = g * 16 + (e >> 10);
        float ga = gamma[c] * rstd, be = beta[c] - mean * ga;
        float4 v = *(const float4*)(xs + e);
        *(uint2*)(hp + e) = make_uint2(bfp(v.x * ga + be, v.y * ga + be),
                                       bfp(v.z * ga + be, v.w * ga + be));
    }
}

// ---------------- 2/4) bf16 GEMM, 3-stage cp.async, 1 sync/chunk ----------------
// smem: A 3x10240 | B 3x8704 = 56832
#define G_BOFF 30720
template<int MODE>
__global__ __launch_bounds__(256, 2) void gemm_mma(
    const __nv_bfloat16* __restrict__ Wall,
    const float* __restrict__ b0v, const float* __restrict__ b1v,
    const __nv_bfloat16* __restrict__ Bg, const float* __restrict__ xres,
    void* __restrict__ Cout)
{
    extern __shared__ unsigned char gsm[];
    const uint32_t sb = s2u(gsm);
    const int tid = threadIdx.x, lane = tid & 31, wid = tid >> 5;
    const int wm = wid & 3, wn = wid >> 2;
    const int n0 = blockIdx.x * 128, m0 = blockIdx.y * 128, b = blockIdx.z;

    const __nv_bfloat16* A;
    const float* bias;
    if (MODE == 0) {
        A = Wall + (size_t)m0 * 512;
        bias = (m0 < 512) ? (b0v + m0) : (b1v + (m0 - 512));
    } else {
        A = Wall + (size_t)(1536 + m0) * 512;
        bias = b0v + m0;
    }
    const __nv_bfloat16* Bb = Bg + (size_t)b * 512 * 1024 + n0;

    float acc[2][8][4];
    #pragma unroll
    for (int mt = 0; mt < 2; mt++)
        #pragma unroll
        for (int nt = 0; nt < 8; nt++)
            #pragma unroll
            for (int r = 0; r < 4; r++) acc[mt][nt][r] = 0.f;

    const int ae_r = tid >> 1, ae_c = (tid & 1) * 16;
    const int be_k = tid >> 3, be_c = (tid & 7) * 16;
    const uint32_t afill = sb + ae_r * 80 + ae_c * 2;
    const uint32_t bfill = sb + G_BOFF + be_k * 272 + be_c * 2;
    const __nv_bfloat16* agp = A + (size_t)ae_r * 512 + ae_c;
    const __nv_bfloat16* bgp = Bb + (size_t)be_k * 1024 + be_c;

    #define FILL(st, kc) do { \
        CPAu(afill + (st) * 10240,      agp + (kc)); \
        CPAu(afill + (st) * 10240 + 16, agp + (kc) + 8); \
        CPAu(bfill + (st) * 8704,       bgp + (size_t)(kc) * 1024); \
        CPAu(bfill + (st) * 8704 + 16,  bgp + (size_t)(kc) * 1024 + 8); \
        CPCOMMIT(); } while (0)

    const uint32_t afrag = sb + (wm*32 + ((lane>>3)&1)*8 + (lane&7)) * 80 + ((lane>>4)*8) * 2;
    const uint32_t bfrag = sb + G_BOFF + (((lane>>3)&1)*8 + (lane&7)) * 272 + (wn*64 + (lane>>4)*8) * 2;

    FILL(0, 0); FILL(1, 32);
    #pragma unroll 1
    for (int i = 0; i < 16; i++) {
        const int st = i - (i / 3) * 3;
        if (i < 15) CPWAIT(1); else CPWAIT(0);
        __syncthreads();
        if (i + 2 < 16) {
            const int st2 = (i + 2) - ((i + 2) / 3) * 3;
            FILL(st2, (i + 2) * 32);
        }
        const uint32_t aoff = afrag + st * 10240, boff = bfrag + st * 8704;
        #pragma unroll
        for (int ks = 0; ks < 2; ks++) {
            const int kk = ks * 16;
            uint32_t af[2][4];
            #pragma unroll
            for (int mt = 0; mt < 2; mt++)
                ldm4(af[mt], aoff + mt * (16 * 80) + kk * 2);
            uint32_t bf_[4][4];
            #pragma unroll
            for (int j4 = 0; j4 < 4; j4++)
                ldm4t(bf_[j4], boff + kk * 272 + j4 * 32);
            #pragma unroll
            for (int nt = 0; nt < 8; nt++) {
                uint32_t b0 = bf_[nt>>1][(nt&1)*2], b1 = bf_[nt>>1][(nt&1)*2 + 1];
                mma16(acc[0][nt], af[0], b0, b1);
                mma16(acc[1][nt], af[1], b0, b1);
            }
        }
    }

    const float sc = (MODE == 0 && m0 < 1024) ? QK_SCALE : 1.0f;
    #pragma unroll
    for (int mt = 0; mt < 2; mt++) {
        const int loc = wm * 32 + mt * 16 + (lane >> 2);
        const int m = m0 + loc;
        const float bi0 = bias[loc], bi1 = bias[loc + 8];
        #pragma unroll
        for (int nt = 0; nt < 8; nt++) {
            const int nc = wn * 64 + nt * 8 + 2 * (lane & 3);
            float v00 = (acc[mt][nt][0] + bi0) * sc, v01 = (acc[mt][nt][1] + bi0) * sc;
            float v10 = (acc[mt][nt][2] + bi1) * sc, v11 = (acc[mt][nt][3] + bi1) * sc;
            if (MODE == 0) {
                __nv_bfloat16* row0 = (__nv_bfloat16*)Cout + ((size_t)b * 1536 + m) * 1024 + n0 + nc;
                *(uint32_t*)row0              = bfp(v00, v01);
                *(uint32_t*)(row0 + 8 * 1024) = bfp(v10, v11);
            } else {
                float* row0 = (float*)Cout + ((size_t)b * 512 + m) * 1024 + n0 + nc;
                const float* xr0 = xres + ((size_t)b * 512 + m) * 1024 + n0 + nc;
                float2 x0 = *(const float2*)xr0, x1 = *(const float2*)(xr0 + 8 * 1024);
                *(float2*)row0              = make_float2(v00 + x0.x, v01 + x0.y);
                *(float2*)(row0 + 8 * 1024) = make_float2(v10 + x1.x, v11 + x1.y);
            }
        }
    }
    #undef FILL
}

// ---------------- 3) FA2 attention: reg-P, ones-MMA row sums, frag prefetch ----------------
// smem: K bufs at 0/17408/34816, V bufs at 52224/69632/87040 = 104448; Q overlays K buf 0.
#define A_VOFF 52224
#define ONES2  0x3F803F80u
__global__ __launch_bounds__(256, 2) void attn_mma(const __nv_bfloat16* __restrict__ qkv,
                                                   __nv_bfloat16* __restrict__ att)
{
    extern __shared__ unsigned char dsm[];
    const uint32_t sb = s2u(dsm);
    const int tid = threadIdx.x, lane = tid & 31, wid = tid >> 5;
    const int b = blockIdx.z, h = blockIdx.y, q0 = blockIdx.x * 128;

    const __nv_bfloat16* Qg = qkv + ((size_t)b * 1536 + h * 64) * 1024 + q0;
    const __nv_bfloat16* Kg = qkv + ((size_t)b * 1536 + 512 + h * 64) * 1024;
    const __nv_bfloat16* Vg = qkv + ((size_t)b * 1536 + 1024 + h * 64) * 1024;

    // Q into K-buf-0 region, extract fragments, then recycle
    __nv_bfloat16 (*Qs)[136] = (__nv_bfloat16(*)[136])(dsm);
    #pragma unroll
    for (int it = 0; it < 4; it++) {
        int idx = tid + it * 256, d = idx >> 4, c8 = (idx & 15) * 8;
        *(uint4*)&Qs[d][c8] = *(const uint4*)(Qg + (size_t)d * 1024 + c8);
    }
    __syncthreads();
    uint32_t qf[4][4];
    #pragma unroll
    for (int ks = 0; ks < 4; ks++)
        ldm4t(qf[ks], sb + (ks*16 + (lane>>4)*8 + (lane&7)) * 272 + (wid*16 + ((lane>>3)&1)*8) * 2);
    __syncthreads();

    const int fd = tid >> 2, fc = (tid & 3) * 32;
    const uint32_t kfill = sb + fd * 272 + fc * 2;
    const uint32_t vfill = sb + A_VOFF + fd * 272 + fc * 2;
    const __nv_bfloat16* kgp = Kg + (size_t)fd * 1024 + fc;
    const __nv_bfloat16* vgp = Vg + (size_t)fd * 1024 + fc;
    #define FILLKV(stoff, s0) do { \
        _Pragma("unroll") \
        for (int j = 0; j < 4; j++) { \
            CPAu(kfill + (stoff) + j * 16, kgp + (s0) + j * 8); \
            CPAu(vfill + (stoff) + j * 16, vgp + (s0) + j * 8); } \
        CPCOMMIT(); } while (0)

    const uint32_t kfrag = sb + (((lane>>3)&1)*8 + (lane&7)) * 272 + ((lane>>4)*8) * 2;
    const uint32_t vfrag = sb + A_VOFF + ((lane>>4)*8 + (lane&7)) * 272 + (((lane>>3)&1)*8) * 2;

    float o_acc[8][4];
    #pragma unroll
    for (int nt = 0; nt < 8; nt++)
        #pragma unroll
        for (int r = 0; r < 4; r++) o_acc[nt][r] = 0.f;
    float sum_acc[4] = {0.f, 0.f, 0.f, 0.f};     // ones-MMA accumulator: c0=row r sum, c2=row r+8 sum

    FILLKV(0, 0); FILLKV(17408, 128);
    #pragma unroll 1
    for (int ck = 0; ck < 8; ck++) {
        const int st = ck - (ck / 3) * 3;
        if (ck < 7) CPWAIT(1); else CPWAIT(0);
        __syncthreads();
        if (ck + 2 < 8) {
            const int st2 = (ck + 2) - ((ck + 2) / 3) * 3;
            FILLKV(st2 * 17408, (ck + 2) * 128);
        }
        const uint32_t koff = kfrag + st * 17408, voff = vfrag + st * 17408;

        #pragma unroll
        for (int hf = 0; hf < 2; hf++) {
            const int nb = hf * 64;
            float s_acc[8][4];
            #pragma unroll
            for (int nt = 0; nt < 8; nt++)
                #pragma unroll
                for (int r = 0; r < 4; r++) s_acc[nt][r] = 0.f;

            // S: prefetch kf one k-step ahead
            uint32_t kf[2][4][4];
            #pragma unroll
            for (int j4 = 0; j4 < 4; j4++)
                ldm4t(kf[0][j4], koff + (nb + j4 * 16) * 2);
            #pragma unroll
            for (int ks = 0; ks < 4; ks++) {
                const int cur = ks & 1;
                if (ks < 3) {
                    #pragma unroll
                    for (int j4 = 0; j4 < 4; j4++)
                        ldm4t(kf[cur ^ 1][j4], koff + (ks + 1) * (16 * 272) + (nb + j4 * 16) * 2);
                }
                #pragma unroll
                for (int nt = 0; nt < 8; nt++)
                    mma16(s_acc[nt], qf[ks], kf[cur][nt>>1][(nt&1)*2], kf[cur][nt>>1][(nt&1)*2 + 1]);
            }

            // exp -> PV A-fragments
            uint32_t pf[4][4];
            #pragma unroll
            for (int j = 0; j < 4; j++) {
                float e0 = __expf(s_acc[2*j][0]),   e1 = __expf(s_acc[2*j][1]);
                float e2 = __expf(s_acc[2*j][2]),   e3 = __expf(s_acc[2*j][3]);
                float f0 = __expf(s_acc[2*j+1][0]), f1 = __expf(s_acc[2*j+1][1]);
                float f2 = __expf(s_acc[2*j+1][2]), f3 = __expf(s_acc[2*j+1][3]);
                pf[j][0] = bfp(e0, e1); pf[j][1] = bfp(e2, e3);
                pf[j][2] = bfp(f0, f1); pf[j][3] = bfp(f2, f3);
            }

            // PV with prefetched vb; ones-MMA accumulates row sums
            uint32_t vb[2][4][4];
            #pragma unroll
            for (int j4 = 0; j4 < 4; j4++)
                ldm4(vb[0][j4], voff + j4 * (16 * 272) + nb * 2);
            #pragma unroll
            for (int j = 0; j < 4; j++) {
                const int cur = j & 1;
                if (j < 3) {
                    #pragma unroll
                    for (int j4 = 0; j4 < 4; j4++)
                        ldm4(vb[cur ^ 1][j4], voff + j4 * (16 * 272) + (nb + (j + 1) * 16) * 2);
                }
                #pragma unroll
                for (int nt = 0; nt < 8; nt++)
                    mma16(o_acc[nt], pf[j], vb[cur][nt>>1][(nt&1)*2], vb[cur][nt>>1][(nt&1)*2 + 1]);
                mma16(sum_acc, pf[j], ONES2, ONES2);
            }
        }
    }

    const float ilo = 1.f / sum_acc[0], ihi = 1.f / sum_acc[2];   // quad-uniform, no shfl needed

    __syncthreads();
    float* Osm = (float*)dsm;
    const int rlo = wid * 16 + (lane >> 2);
    #pragma unroll
    for (int nt = 0; nt < 8; nt++) {
        const int d = nt * 8 + 2 * (lane & 3);
        Osm[(size_t)d * 136 + rlo]           = o_acc[nt][0] * ilo;
        Osm[(size_t)(d + 1) * 136 + rlo]     = o_acc[nt][1] * ilo;
        Osm[(size_t)d * 136 + rlo + 8]       = o_acc[nt][2] * ihi;
        Osm[(size_t)(d + 1) * 136 + rlo + 8] = o_acc[nt][3] * ihi;
    }
    __syncthreads();
    __nv_bfloat16* Og = att + ((size_t)b * 512 + h * 64) * 1024 + q0;
    #pragma unroll
    for (int it = 0; it < 8; it++) {
        int idx = tid + it * 256, d = idx >> 5, t4 = (idx & 31) * 4;
        const float* src = &Osm[(size_t)d * 136 + t4];
        *(uint2*)(Og + (size_t)d * 1024 + t4) = make_uint2(bfp(src[0], src[1]), bfp(src[2], src[3]));
    }
    #undef FILLKV
}

// ---------------- launch ----------------
extern "C" void kernel_launch(void* const* d_in, const int* in_sizes, int n_in,
                              void* d_out, int out_size)
{
    const float* x     = (const float*)d_in[0];
    const float* gamma = (const float*)d_in[1];
    const float* beta  = (const float*)d_in[2];
    const float* Wq    = (const float*)d_in[3];
    const float* bq    = (const float*)d_in[4];
    const float* Wkv   = (const float*)d_in[5];
    const float* bkv   = (const float*)d_in[6];
    const float* Wo    = (const float*)d_in[7];
    const float* bo    = (const float*)d_in[8];

    __nv_bfloat16* hn;  cudaGetSymbolAddress((void**)&hn,  g_hn);
    __nv_bfloat16* qkv; cudaGetSymbolAddress((void**)&qkv, g_qkv);
    __nv_bfloat16* att; cudaGetSymbolAddress((void**)&att, g_att);
    __nv_bfloat16* w;   cudaGetSymbolAddress((void**)&w,   g_w);

    prep_kernel<<<1024, 256>>>(Wq, Wkv, Wo, w);
    {
        cudaFuncSetAttribute(gn_kernel, cudaFuncAttributeMaxDynamicSharedMemorySize, 65536);
        gn_kernel<<<256, 256, 65536>>>(x, gamma, beta, hn);
    }
    {
        cudaFuncSetAttribute(gemm_mma<0>, cudaFuncAttributeMaxDynamicSharedMemorySize, 56832);
        dim3 grid(8, 12, BATCH);
        gemm_mma<0><<<grid, 256, 56832>>>(w, bq, bkv, hn, nullptr, qkv);
    }
    {
        cudaFuncSetAttribute(attn_mma, cudaFuncAttributeMaxDynamicSharedMemorySize, 104448);
        dim3 grid(8, 8, BATCH);
        attn_mma<<<grid, 256, 104448>>>(qkv, att);
    }
    {
        cudaFuncSetAttribute(gemm_mma<1>, cudaFuncAttributeMaxDynamicSharedMemorySize, 56832);
        dim3 grid(8, 4, BATCH);
        gemm_mma<1><<<grid, 256, 56832>>>(w, bo, nullptr, att, x, d_out);
    }
}

// round 11
// speedup vs baseline: 9.1300x; 1.0436x over previous
#include <cuda_runtime.h>
#include <cuda_bf16.h>
#include <cstdint>

#define BATCH 8
#define LSEQ  1024
#define QK_SCALE 0.125f

// ---------------- scratch (no allocs allowed) ----------------
__device__ __nv_bfloat16 g_hn [(size_t)BATCH*512*LSEQ];    // [b][c][L]
__device__ __nv_bfloat16 g_qkv[(size_t)BATCH*1536*LSEQ];   // rows 0-511 q*s, 512-1023 k*s, 1024-1535 v
__device__ __nv_bfloat16 g_att[(size_t)BATCH*512*LSEQ];    // [b][inner][L]
__device__ __nv_bfloat16 g_w  [(size_t)2048*512];          // bf16 weights: Wq | Wkv | Wo

// ---------------- helpers ----------------
__device__ __forceinline__ uint32_t s2u(const void* p){
    uint32_t a;
    asm("{ .reg .u64 t; cvta.to.shared.u64 t, %1; cvt.u32.u64 %0, t; }" : "=r"(a) : "l"(p));
    return a;
}
__device__ __forceinline__ void ldm4(uint32_t* r, uint32_t a){
    asm volatile("ldmatrix.sync.aligned.m8n8.x4.shared.b16 {%0,%1,%2,%3}, [%4];"
        : "=r"(r[0]),"=r"(r[1]),"=r"(r[2]),"=r"(r[3]) : "r"(a));
}
__device__ __forceinline__ void ldm2t(uint32_t* r, uint32_t a){
    asm volatile("ldmatrix.sync.aligned.m8n8.x2.trans.shared.b16 {%0,%1}, [%2];"
        : "=r"(r[0]),"=r"(r[1]) : "r"(a));
}
__device__ __forceinline__ void ldm4t(uint32_t* r, uint32_t a){
    asm volatile("ldmatrix.sync.aligned.m8n8.x4.trans.shared.b16 {%0,%1,%2,%3}, [%4];"
        : "=r"(r[0]),"=r"(r[1]),"=r"(r[2]),"=r"(r[3]) : "r"(a));
}
__device__ __forceinline__ void mma16(float* d, const uint32_t* a, uint32_t b0, uint32_t b1){
    asm volatile("mma.sync.aligned.m16n8k16.row.col.f32.bf16.bf16.f32 "
        "{%0,%1,%2,%3}, {%4,%5,%6,%7}, {%8,%9}, {%0,%1,%2,%3};"
        : "+f"(d[0]),"+f"(d[1]),"+f"(d[2]),"+f"(d[3])
        : "r"(a[0]),"r"(a[1]),"r"(a[2]),"r"(a[3]), "r"(b0),"r"(b1));
}
__device__ __forceinline__ uint32_t bfp(float x, float y){
    __nv_bfloat162 t = __floats2bfloat162_rn(x, y);
    return *(uint32_t*)&t;
}
#define CPAu(s, g)  asm volatile("cp.async.cg.shared.global [%0], [%1], 16;" :: "r"(s), "l"(g))
#define CPCOMMIT()  asm volatile("cp.async.commit_group;" ::: "memory")
#define CPWAIT(n)   asm volatile("cp.async.wait_group %0;" :: "n"(n) : "memory")

// ---------------- 0) weight prep: fp32 -> bf16 ----------------
__global__ __launch_bounds__(256) void prep_kernel(const float* __restrict__ Wq,
    const float* __restrict__ Wkv, const float* __restrict__ Wo,
    __nv_bfloat16* __restrict__ w)
{
    const size_t off = ((size_t)blockIdx.x * 256 + threadIdx.x) * 4;
    const float* src;
    if (off < (size_t)512 * 512)            src = Wq + off;
    else if (off < (size_t)1536 * 512)      src = Wkv + (off - (size_t)512 * 512);
    else                                    src = Wo + (off - (size_t)1536 * 512);
    float4 v = *(const float4*)src;
    *(uint2*)(w + off) = make_uint2(bfp(v.x, v.y), bfp(v.z, v.w));
}

// ---------------- 1) GroupNorm (one-pass, smem-cached) -> bf16 hn[b][c][L] ----------------
__global__ __launch_bounds__(256) void gn_kernel(const float* __restrict__ x,
    const float* __restrict__ gamma, const float* __restrict__ beta,
    __nv_bfloat16* __restrict__ hn)
{
    extern __shared__ float xs[];
    const int b = blockIdx.x >> 5, g = blockIdx.x & 31;
    const float* xp = x + ((size_t)b * 512 + g * 16) * LSEQ;
    __nv_bfloat16* hp = hn + ((size_t)b * 512 + g * 16) * LSEQ;
    float s1 = 0.f, s2 = 0.f;
    for (int e = threadIdx.x * 4; e < 16 * LSEQ; e += 1024) {
        float4 v = *(const float4*)(xp + e);
        *(float4*)(xs + e) = v;
        s1 += v.x + v.y + v.z + v.w;
        s2 += v.x * v.x + v.y * v.y + v.z * v.z + v.w * v.w;
    }
    __shared__ float r1[32], r2[32];
    #pragma unroll
    for (int o = 16; o > 0; o >>= 1) {
        s1 += __shfl_down_sync(~0u, s1, o); s2 += __shfl_down_sync(~0u, s2, o);
    }
    int wid = threadIdx.x >> 5, lid = threadIdx.x & 31;
    if (lid == 0) { r1[wid] = s1; r2[wid] = s2; }
    __syncthreads();
    if (wid == 0) {
        s1 = (lid < 8) ? r1[lid] : 0.f; s2 = (lid < 8) ? r2[lid] : 0.f;
        #pragma unroll
        for (int o = 4; o > 0; o >>= 1) {
            s1 += __shfl_down_sync(~0u, s1, o); s2 += __shfl_down_sync(~0u, s2, o);
        }
        if (lid == 0) { r1[0] = s1; r2[0] = s2; }
    }
    __syncthreads();
    const float mean = r1[0] * (1.f / 16384.f);
    const float rstd = rsqrtf(r2[0] * (1.f / 16384.f) - mean * mean + 1e-5f);
    for (int e = threadIdx.x * 4; e < 16 * LSEQ; e += 1024) {
        int c = g * 16 + (e >> 10);
        float ga = gamma[c] * rstd, be = beta[c] - mean * ga;
        float4 v = *(const float4*)(xs + e);
        *(uint2*)(hp + e) = make_uint2(bfp(v.x * ga + be, v.y * ga + be),
                                       bfp(v.z * ga + be, v.w * ga + be));
    }
}

// ---------------- 2/4) bf16 GEMM, 3-stage cp.async, 1 sync/chunk ----------------
// smem: A 3x10240 | B 3x8704 = 56832
#define G_BOFF 30720
template<int MODE>
__global__ __launch_bounds__(256, 2) void gemm_mma(
    const __nv_bfloat16* __restrict__ Wall,
    const float* __restrict__ b0v, const float* __restrict__ b1v,
    const __nv_bfloat16* __restrict__ Bg, const float* __restrict__ xres,
    void* __restrict__ Cout)
{
    extern __shared__ unsigned char gsm[];
    const uint32_t sb = s2u(gsm);
    const int tid = threadIdx.x, lane = tid & 31, wid = tid >> 5;
    const int wm = wid & 3, wn = wid >> 2;
    const int n0 = blockIdx.x * 128, m0 = blockIdx.y * 128, b = blockIdx.z;

    const __nv_bfloat16* A;
    const float* bias;
    if (MODE == 0) {
        A = Wall + (size_t)m0 * 512;
        bias = (m0 < 512) ? (b0v + m0) : (b1v + (m0 - 512));
    } else {
        A = Wall + (size_t)(1536 + m0) * 512;
        bias = b0v + m0;
    }
    const __nv_bfloat16* Bb = Bg + (size_t)b * 512 * 1024 + n0;

    float acc[2][8][4];
    #pragma unroll
    for (int mt = 0; mt < 2; mt++)
        #pragma unroll
        for (int nt = 0; nt < 8; nt++)
            #pragma unroll
            for (int r = 0; r < 4; r++) acc[mt][nt][r] = 0.f;

    const int ae_r = tid >> 1, ae_c = (tid & 1) * 16;
    const int be_k = tid >> 3, be_c = (tid & 7) * 16;
    const uint32_t afill = sb + ae_r * 80 + ae_c * 2;
    const uint32_t bfill = sb + G_BOFF + be_k * 272 + be_c * 2;
    const __nv_bfloat16* agp = A + (size_t)ae_r * 512 + ae_c;
    const __nv_bfloat16* bgp = Bb + (size_t)be_k * 1024 + be_c;

    #define FILL(st, kc) do { \
        CPAu(afill + (st) * 10240,      agp + (kc)); \
        CPAu(afill + (st) * 10240 + 16, agp + (kc) + 8); \
        CPAu(bfill + (st) * 8704,       bgp + (size_t)(kc) * 1024); \
        CPAu(bfill + (st) * 8704 + 16,  bgp + (size_t)(kc) * 1024 + 8); \
        CPCOMMIT(); } while (0)

    const uint32_t afrag = sb + (wm*32 + ((lane>>3)&1)*8 + (lane&7)) * 80 + ((lane>>4)*8) * 2;
    const uint32_t bfrag = sb + G_BOFF + (((lane>>3)&1)*8 + (lane&7)) * 272 + (wn*64 + (lane>>4)*8) * 2;

    FILL(0, 0); FILL(1, 32);
    #pragma unroll 1
    for (int i = 0; i < 16; i++) {
        const int st = i - (i / 3) * 3;
        if (i < 15) CPWAIT(1); else CPWAIT(0);
        __syncthreads();
        if (i + 2 < 16) {
            const int st2 = (i + 2) - ((i + 2) / 3) * 3;
            FILL(st2, (i + 2) * 32);
        }
        const uint32_t aoff = afrag + st * 10240, boff = bfrag + st * 8704;
        #pragma unroll
        for (int ks = 0; ks < 2; ks++) {
            const int kk = ks * 16;
            uint32_t af[2][4];
            #pragma unroll
            for (int mt = 0; mt < 2; mt++)
                ldm4(af[mt], aoff + mt * (16 * 80) + kk * 2);
            uint32_t bf_[4][4];
            #pragma unroll
            for (int j4 = 0; j4 < 4; j4++)
                ldm4t(bf_[j4], boff + kk * 272 + j4 * 32);
            #pragma unroll
            for (int nt = 0; nt < 8; nt++) {
                uint32_t b0 = bf_[nt>>1][(nt&1)*2], b1 = bf_[nt>>1][(nt&1)*2 + 1];
                mma16(acc[0][nt], af[0], b0, b1);
                mma16(acc[1][nt], af[1], b0, b1);
            }
        }
    }

    const float sc = (MODE == 0 && m0 < 1024) ? QK_SCALE : 1.0f;
    #pragma unroll
    for (int mt = 0; mt < 2; mt++) {
        const int loc = wm * 32 + mt * 16 + (lane >> 2);
        const int m = m0 + loc;
        const float bi0 = bias[loc], bi1 = bias[loc + 8];
        #pragma unroll
        for (int nt = 0; nt < 8; nt++) {
            const int nc = wn * 64 + nt * 8 + 2 * (lane & 3);
            float v00 = (acc[mt][nt][0] + bi0) * sc, v01 = (acc[mt][nt][1] + bi0) * sc;
            float v10 = (acc[mt][nt][2] + bi1) * sc, v11 = (acc[mt][nt][3] + bi1) * sc;
            if (MODE == 0) {
                __nv_bfloat16* row0 = (__nv_bfloat16*)Cout + ((size_t)b * 1536 + m) * 1024 + n0 + nc;
                *(uint32_t*)row0              = bfp(v00, v01);
                *(uint32_t*)(row0 + 8 * 1024) = bfp(v10, v11);
            } else {
                float* row0 = (float*)Cout + ((size_t)b * 512 + m) * 1024 + n0 + nc;
                const float* xr0 = xres + ((size_t)b * 512 + m) * 1024 + n0 + nc;
                float2 x0 = *(const float2*)xr0, x1 = *(const float2*)(xr0 + 8 * 1024);
                *(float2*)row0              = make_float2(v00 + x0.x, v01 + x0.y);
                *(float2*)(row0 + 8 * 1024) = make_float2(v10 + x1.x, v11 + x1.y);
            }
        }
    }
    #undef FILL
}

// ---------------- 3) FA2 attention: m32 warp tile, 256 q-rows/CTA, n-quarter loop ----------------
// smem: K bufs at 0/17408/34816, V bufs at 52224/69632/87040 = 104448; Q (33792B) overlays K bufs 0-1.
#define A_VOFF 52224
#define ONES2  0x3F803F80u
__global__ __launch_bounds__(256, 1) void attn_mma(const __nv_bfloat16* __restrict__ qkv,
                                                   __nv_bfloat16* __restrict__ att)
{
    extern __shared__ unsigned char dsm[];
    const uint32_t sb = s2u(dsm);
    const int tid = threadIdx.x, lane = tid & 31, wid = tid >> 5;
    const int b = blockIdx.z, h = blockIdx.y, q0 = blockIdx.x * 256;

    const __nv_bfloat16* Qg = qkv + ((size_t)b * 1536 + h * 64) * 1024 + q0;
    const __nv_bfloat16* Kg = qkv + ((size_t)b * 1536 + 512 + h * 64) * 1024;
    const __nv_bfloat16* Vg = qkv + ((size_t)b * 1536 + 1024 + h * 64) * 1024;

    // stage Q [64 d][264-stride, 256 t] over K bufs 0-1; extract warp's m32 A-frags
    __nv_bfloat16* Qs = (__nv_bfloat16*)dsm;
    #pragma unroll
    for (int it = 0; it < 8; it++) {
        int idx = tid + it * 256, d = idx >> 5, c8 = (idx & 31) * 8;
        *(uint4*)(Qs + d * 264 + c8) = *(const uint4*)(Qg + (size_t)d * 1024 + c8);
    }
    __syncthreads();
    uint32_t qf[4][2][4];
    #pragma unroll
    for (int ks = 0; ks < 4; ks++)
        #pragma unroll
        for (int mt = 0; mt < 2; mt++)
            ldm4t(qf[ks][mt], sb + (ks*16 + (lane>>4)*8 + (lane&7)) * 528
                                 + (wid*32 + mt*16 + ((lane>>3)&1)*8) * 2);
    __syncthreads();

    const int fd = tid >> 2, fc = (tid & 3) * 32;
    const uint32_t kfill = sb + fd * 272 + fc * 2;
    const uint32_t vfill = sb + A_VOFF + fd * 272 + fc * 2;
    const __nv_bfloat16* kgp = Kg + (size_t)fd * 1024 + fc;
    const __nv_bfloat16* vgp = Vg + (size_t)fd * 1024 + fc;
    #define FILLKV(stoff, s0) do { \
        _Pragma("unroll") \
        for (int j = 0; j < 4; j++) { \
            CPAu(kfill + (stoff) + j * 16, kgp + (s0) + j * 8); \
            CPAu(vfill + (stoff) + j * 16, vgp + (s0) + j * 8); } \
        CPCOMMIT(); } while (0)

    const uint32_t kfrag = sb + (((lane>>3)&1)*8 + (lane&7)) * 272 + ((lane>>4)*8) * 2;
    const uint32_t vfrag = sb + A_VOFF + ((lane>>4)*8 + (lane&7)) * 272 + (((lane>>3)&1)*8) * 2;

    float o_acc[2][8][4];
    #pragma unroll
    for (int mt = 0; mt < 2; mt++)
        #pragma unroll
        for (int nt = 0; nt < 8; nt++)
            #pragma unroll
            for (int r = 0; r < 4; r++) o_acc[mt][nt][r] = 0.f;
    float sum_acc[2][4] = {{0.f,0.f,0.f,0.f},{0.f,0.f,0.f,0.f}};

    FILLKV(0, 0); FILLKV(17408, 128);
    #pragma unroll 1
    for (int ck = 0; ck < 8; ck++) {
        const int st = ck - (ck / 3) * 3;
        if (ck < 7) CPWAIT(1); else CPWAIT(0);
        __syncthreads();
        if (ck + 2 < 8) {
            const int st2 = (ck + 2) - ((ck + 2) / 3) * 3;
            FILLKV(st2 * 17408, (ck + 2) * 128);
        }
        const uint32_t koff = kfrag + st * 17408, voff = vfrag + st * 17408;

        #pragma unroll
        for (int qt = 0; qt < 4; qt++) {         // n-quarters (s-cols nb..nb+31)
            const int nb = qt * 32;
            float s_acc[2][4][4];
            #pragma unroll
            for (int mt = 0; mt < 2; mt++)
                #pragma unroll
                for (int nt = 0; nt < 4; nt++)
                    #pragma unroll
                    for (int r = 0; r < 4; r++) s_acc[mt][nt][r] = 0.f;
            #pragma unroll
            for (int ks = 0; ks < 4; ks++) {
                uint32_t kf[2][4];
                #pragma unroll
                for (int j4 = 0; j4 < 2; j4++)
                    ldm4t(kf[j4], koff + ks * (16 * 272) + (nb + j4 * 16) * 2);
                #pragma unroll
                for (int nt = 0; nt < 4; nt++) {
                    uint32_t b0 = kf[nt>>1][(nt&1)*2], b1 = kf[nt>>1][(nt&1)*2 + 1];
                    mma16(s_acc[0][nt], qf[ks][0], b0, b1);
                    mma16(s_acc[1][nt], qf[ks][1], b0, b1);
                }
            }
            // exp -> PV A-fragments (accum layout == A-frag layout)
            uint32_t pf[2][2][4];
            #pragma unroll
            for (int mt = 0; mt < 2; mt++)
                #pragma unroll
                for (int j = 0; j < 2; j++) {
                    float e0 = __expf(s_acc[mt][2*j][0]),   e1 = __expf(s_acc[mt][2*j][1]);
                    float e2 = __expf(s_acc[mt][2*j][2]),   e3 = __expf(s_acc[mt][2*j][3]);
                    float f0 = __expf(s_acc[mt][2*j+1][0]), f1 = __expf(s_acc[mt][2*j+1][1]);
                    float f2 = __expf(s_acc[mt][2*j+1][2]), f3 = __expf(s_acc[mt][2*j+1][3]);
                    pf[mt][j][0] = bfp(e0, e1); pf[mt][j][1] = bfp(e2, e3);
                    pf[mt][j][2] = bfp(f0, f1); pf[mt][j][3] = bfp(f2, f3);
                }
            // O += P V^T over this s-quarter (k = 2 k16 steps)
            #pragma unroll
            for (int j = 0; j < 2; j++) {
                const int kk = nb + j * 16;
                uint32_t vb[4][4];
                #pragma unroll
                for (int j4 = 0; j4 < 4; j4++)
                    ldm4(vb[j4], voff + j4 * (16 * 272) + kk * 2);
                #pragma unroll
                for (int nt = 0; nt < 8; nt++) {
                    uint32_t b0 = vb[nt>>1][(nt&1)*2], b1 = vb[nt>>1][(nt&1)*2 + 1];
                    mma16(o_acc[0][nt], pf[0][j], b0, b1);
                    mma16(o_acc[1][nt], pf[1][j], b0, b1);
                }
                mma16(sum_acc[0], pf[0][j], ONES2, ONES2);
                mma16(sum_acc[1], pf[1][j], ONES2, ONES2);
            }
        }
    }

    const float il0 = 1.f / sum_acc[0][0], ih0 = 1.f / sum_acc[0][2];
    const float il1 = 1.f / sum_acc[1][0], ih1 = 1.f / sum_acc[1][2];

    // normalize + transpose via smem (float [64][264]) + bf16 store
    __syncthreads();
    float* Osm = (float*)dsm;
    #pragma unroll
    for (int mt = 0; mt < 2; mt++) {
        const int rl = wid * 32 + mt * 16 + (lane >> 2);
        const float il = mt ? il1 : il0, ih = mt ? ih1 : ih0;
        #pragma unroll
        for (int nt = 0; nt < 8; nt++) {
            const int d = nt * 8 + 2 * (lane & 3);
            Osm[(size_t)d * 264 + rl]           = o_acc[mt][nt][0] * il;
            Osm[(size_t)(d + 1) * 264 + rl]     = o_acc[mt][nt][1] * il;
            Osm[(size_t)d * 264 + rl + 8]       = o_acc[mt][nt][2] * ih;
            Osm[(size_t)(d + 1) * 264 + rl + 8] = o_acc[mt][nt][3] * ih;
        }
    }
    __syncthreads();
    __nv_bfloat16* Og = att + ((size_t)b * 512 + h * 64) * 1024 + q0;
    #pragma unroll
    for (int it = 0; it < 16; it++) {
        int idx = tid + it * 256, d = idx >> 6, t4 = (idx & 63) * 4;
        const float* src = Osm + (size_t)d * 264 + t4;
        *(uint2*)(Og + (size_t)d * 1024 + t4) = make_uint2(bfp(src[0], src[1]), bfp(src[2], src[3]));
    }
    #undef FILLKV
}

// ---------------- launch ----------------
extern "C" void kernel_launch(void* const* d_in, const int* in_sizes, int n_in,
                              void* d_out, int out_size)
{
    const float* x     = (const float*)d_in[0];
    const float* gamma = (const float*)d_in[1];
    const float* beta  = (const float*)d_in[2];
    const float* Wq    = (const float*)d_in[3];
    const float* bq    = (const float*)d_in[4];
    const float* Wkv   = (const float*)d_in[5];
    const float* bkv   = (const float*)d_in[6];
    const float* Wo    = (const float*)d_in[7];
    const float* bo    = (const float*)d_in[8];

    __nv_bfloat16* hn;  cudaGetSymbolAddress((void**)&hn,  g_hn);
    __nv_bfloat16* qkv; cudaGetSymbolAddress((void**)&qkv, g_qkv);
    __nv_bfloat16* att; cudaGetSymbolAddress((void**)&att, g_att);
    __nv_bfloat16* w;   cudaGetSymbolAddress((void**)&w,   g_w);

    prep_kernel<<<1024, 256>>>(Wq, Wkv, Wo, w);
    {
        cudaFuncSetAttribute(gn_kernel, cudaFuncAttributeMaxDynamicSharedMemorySize, 65536);
        gn_kernel<<<256, 256, 65536>>>(x, gamma, beta, hn);
    }
    {
        cudaFuncSetAttribute(gemm_mma<0>, cudaFuncAttributeMaxDynamicSharedMemorySize, 56832);
        dim3 grid(8, 12, BATCH);
        gemm_mma<0><<<grid, 256, 56832>>>(w, bq, bkv, hn, nullptr, qkv);
    }
    {
        cudaFuncSetAttribute(attn_mma, cudaFuncAttributeMaxDynamicSharedMemorySize, 104448);
        dim3 grid(4, 8, BATCH);
        attn_mma<<<grid, 256, 104448>>>(qkv, att);
    }
    {
        cudaFuncSetAttribute(gemm_mma<1>, cudaFuncAttributeMaxDynamicSharedMemorySize, 56832);
        dim3 grid(8, 4, BATCH);
        gemm_mma<1><<<grid, 256, 56832>>>(w, bo, nullptr, att, x, d_out);
    }
}